// round 10
// baseline (speedup 1.0000x reference)
#include <cuda_runtime.h>
#include <cuda_bf16.h>

#define BB 8
#define TT 512
#define CC 128
#define HH 1024
#define GBLK 148
#define GW 7

typedef unsigned long long ull;

// ---------------- static scratch ----------------
__device__ float g_xg[BB * TT * 3 * HH];
__device__ float g_h[2][BB * HH];
__device__ float g_emb2[BB * CC * TT * 8];
__device__ float g_x3[BB * CC * TT * 8];
__device__ float g_e3x[BB * CC * TT * 16];
__device__ float g_x2[BB * CC * TT * 16];
__device__ float g_e2x[BB * CC * TT * 32];
__device__ float g_x1[BB * CC * TT * 32];
__device__ float g_e1x[BB * CC * TT * 64];
__device__ unsigned short g_Ah[BB * TT * HH];
__device__ unsigned short g_Al[BB * TT * HH];
__device__ unsigned short g_Wh[3 * HH * HH];
__device__ unsigned short g_Wl[3 * HH * HH];
__device__ unsigned short g_pwh[4 * CC * CC];   // split 1x1 weights [w3p,w2p,w1p,w0p]
__device__ unsigned short g_pwl[4 * CC * CC];
__device__ unsigned short g_cwh[3 * 3 * CC * CC]; // split convt weights [layer][tap][oc][ic]
__device__ unsigned short g_cwl[3 * 3 * CC * CC];
__device__ unsigned g_bar_count;
__device__ unsigned g_bar_gen;

// ---------------- barrier state reset (per launch) ----------------
__global__ void k_reset()
{
    if (threadIdx.x == 0) { g_bar_count = 0; g_bar_gen = 0; }
}

// ---------------- acquire/release grid barrier ----------------
__device__ __forceinline__ void grid_barrier(unsigned my_gen)
{
    __syncthreads();
    if (threadIdx.x == 0) {
        unsigned arr;
        asm volatile("atom.add.release.gpu.u32 %0, [%1], 1;"
                     : "=r"(arr) : "l"(&g_bar_count) : "memory");
        if (arr == GBLK - 1) {
            g_bar_count = 0;
            asm volatile("st.release.gpu.u32 [%0], %1;"
                         :: "l"(&g_bar_gen), "r"(my_gen) : "memory");
        } else {
            unsigned cur;
            do {
                asm volatile("ld.acquire.gpu.u32 %0, [%1];"
                             : "=r"(cur) : "l"(&g_bar_gen) : "memory");
            } while ((int)(cur - my_gen) < 0);
        }
    }
    __syncthreads();
}

// ---------------- splitting helpers ----------------
__device__ __forceinline__ void split1(float v, unsigned short& h, unsigned short& l)
{
    __nv_bfloat16 bh = __float2bfloat16(v);
    float r = v - __bfloat162float(bh);
    __nv_bfloat16 bl = __float2bfloat16(r);
    h = *(unsigned short*)&bh;
    l = *(unsigned short*)&bl;
}

// ---------------- bf16 hi/lo split: fp32 tensor -> (hi, lo) ----------------
__global__ __launch_bounds__(256) void k_split(const float4* __restrict__ src,
                                               ushort4* __restrict__ hi,
                                               ushort4* __restrict__ lo,
                                               int n4)
{
    int i = blockIdx.x * 256 + threadIdx.x;
    if (i >= n4) return;
    float4 v = src[i];
    float f[4] = { v.x, v.y, v.z, v.w };
    unsigned short h[4], l[4];
#pragma unroll
    for (int q = 0; q < 4; ++q) split1(f[q], h[q], l[q]);
    hi[i] = make_ushort4(h[0], h[1], h[2], h[3]);
    lo[i] = make_ushort4(l[0], l[1], l[2], l[3]);
}

// ---------------- split 1x1 conv weights (4 layers, [oc][ic]) ----------------
__global__ __launch_bounds__(256) void k_split_pw(const float* __restrict__ w3,
                                                  const float* __restrict__ w2,
                                                  const float* __restrict__ w1,
                                                  const float* __restrict__ w0)
{
    int idx = blockIdx.x * 256 + threadIdx.x;   // < 65536
    int t = idx >> 14, e = idx & 16383;
    const float* src = (t == 0) ? w3 : (t == 1) ? w2 : (t == 2) ? w1 : w0;
    unsigned short h, l;
    split1(src[e], h, l);
    g_pwh[idx] = h; g_pwl[idx] = l;
}

// ---------------- split convt weights: (oc,ic,tap) -> [lyr][tap][oc][ic] ------
__global__ __launch_bounds__(256) void k_split_cw(const float* __restrict__ wt3,
                                                  const float* __restrict__ wt2,
                                                  const float* __restrict__ wt1)
{
    int idx = blockIdx.x * 256 + threadIdx.x;   // < 147456
    if (idx >= 3 * 49152) return;
    int lyr = idx / 49152, r = idx % 49152;
    int tap = r >> 14, oc = (r >> 7) & 127, ic = r & 127;
    const float* src = (lyr == 0) ? wt3 : (lyr == 1) ? wt2 : wt1;
    unsigned short h, l;
    split1(src[(oc * CC + ic) * 3 + tap], h, l);
    g_cwh[idx] = h; g_cwl[idx] = l;
}

// ---------------- mma helpers (sm_80-baseline PTX) ----------------
__device__ __forceinline__ unsigned smem_u32(const void* p)
{
    unsigned a;
    asm("{ .reg .u64 t; cvta.to.shared.u64 t, %1; cvt.u32.u64 %0, t; }"
        : "=r"(a) : "l"(p));
    return a;
}
__device__ __forceinline__ void ldsm4(unsigned* r, unsigned addr)
{
    asm volatile("ldmatrix.sync.aligned.m8n8.x4.shared.b16 {%0,%1,%2,%3}, [%4];"
        : "=r"(r[0]), "=r"(r[1]), "=r"(r[2]), "=r"(r[3]) : "r"(addr));
}
__device__ __forceinline__ void ldsm2(unsigned* r, unsigned addr)
{
    asm volatile("ldmatrix.sync.aligned.m8n8.x2.shared.b16 {%0,%1}, [%2];"
        : "=r"(r[0]), "=r"(r[1]) : "r"(addr));
}
__device__ __forceinline__ void mma16816(float* d, const unsigned* a, const unsigned* b)
{
    asm volatile("mma.sync.aligned.m16n8k16.row.col.f32.bf16.bf16.f32 "
        "{%0,%1,%2,%3}, {%4,%5,%6,%7}, {%8,%9}, {%0,%1,%2,%3};"
        : "+f"(d[0]), "+f"(d[1]), "+f"(d[2]), "+f"(d[3])
        : "r"(a[0]), "r"(a[1]), "r"(a[2]), "r"(a[3]), "r"(b[0]), "r"(b[1]));
}

// ---------------- xg = emb @ Wih^T + bih : mma.sync split-bf16 ----------------
__global__ __launch_bounds__(256) void k_xg_mma(const float* __restrict__ bias)
{
    __shared__ __align__(16) unsigned short sAh[128][40];
    __shared__ __align__(16) unsigned short sAl[128][40];
    __shared__ __align__(16) unsigned short sWh[64][40];
    __shared__ __align__(16) unsigned short sWl[64][40];
    int tid = threadIdx.x, lane = tid & 31, wid = tid >> 5;
    int wm = wid >> 1, wn = wid & 1;
    int m0 = blockIdx.y * 128, n0 = blockIdx.x * 64;

    float acc[2][4][4];
#pragma unroll
    for (int mi = 0; mi < 2; ++mi)
#pragma unroll
        for (int ni = 0; ni < 4; ++ni)
#pragma unroll
            for (int q = 0; q < 4; ++q) acc[mi][ni][q] = 0.f;

    for (int kc = 0; kc < HH; kc += 32) {
        __syncthreads();
#pragma unroll
        for (int i = 0; i < 6; ++i) {
            int idx = tid + i * 256;
            const uint4* src;
            unsigned short* dst;
            if (idx < 512) {
                int row = idx >> 2, c8 = (idx & 3) * 8;
                src = (const uint4*)&g_Ah[(size_t)(m0 + row) * HH + kc + c8];
                dst = &sAh[row][c8];
            } else if (idx < 1024) {
                int e = idx - 512;
                int row = e >> 2, c8 = (e & 3) * 8;
                src = (const uint4*)&g_Al[(size_t)(m0 + row) * HH + kc + c8];
                dst = &sAl[row][c8];
            } else if (idx < 1280) {
                int e = idx - 1024;
                int row = e >> 2, c8 = (e & 3) * 8;
                src = (const uint4*)&g_Wh[(size_t)(n0 + row) * HH + kc + c8];
                dst = &sWh[row][c8];
            } else {
                int e = idx - 1280;
                int row = e >> 2, c8 = (e & 3) * 8;
                src = (const uint4*)&g_Wl[(size_t)(n0 + row) * HH + kc + c8];
                dst = &sWl[row][c8];
            }
            *(uint4*)dst = *src;
        }
        __syncthreads();

#pragma unroll
        for (int ks = 0; ks < 2; ++ks) {
            int k0 = ks * 16;
            unsigned ah[2][4], al[2][4];
#pragma unroll
            for (int mi = 0; mi < 2; ++mi) {
                int m = wm * 32 + mi * 16 + (lane & 15);
                int kk = k0 + (lane >> 4) * 8;
                ldsm4(ah[mi], smem_u32(&sAh[m][kk]));
                ldsm4(al[mi], smem_u32(&sAl[m][kk]));
            }
            unsigned bh[4][2], bl[4][2];
#pragma unroll
            for (int ni = 0; ni < 4; ++ni) {
                int r = lane & 15;
                int n = wn * 32 + ni * 8 + (r & 7);
                int kk = k0 + (r >> 3) * 8;
                ldsm2(bh[ni], smem_u32(&sWh[n][kk]));
                ldsm2(bl[ni], smem_u32(&sWl[n][kk]));
            }
#pragma unroll
            for (int mi = 0; mi < 2; ++mi)
#pragma unroll
                for (int ni = 0; ni < 4; ++ni) {
                    mma16816(acc[mi][ni], ah[mi], bh[ni]);
                    mma16816(acc[mi][ni], ah[mi], bl[ni]);
                    mma16816(acc[mi][ni], al[mi], bh[ni]);
                }
        }
    }
    int gr = lane >> 2, gc = (lane & 3) * 2;
#pragma unroll
    for (int mi = 0; mi < 2; ++mi)
#pragma unroll
        for (int ni = 0; ni < 4; ++ni) {
            int m = m0 + wm * 32 + mi * 16 + gr;
            int n = n0 + wn * 32 + ni * 8 + gc;
            float b0 = bias[n], b1 = bias[n + 1];
            float2 v0 = { acc[mi][ni][0] + b0, acc[mi][ni][1] + b1 };
            float2 v1 = { acc[mi][ni][2] + b0, acc[mi][ni][3] + b1 };
            *(float2*)&g_xg[(size_t)m * (3 * HH) + n] = v0;
            *(float2*)&g_xg[(size_t)(m + 8) * (3 * HH) + n] = v1;
        }
}

// ---------------- persistent GRU: 148 blocks x 224 thr, scalar reg Whh --------
__global__ __launch_bounds__(224) void k_gru(const float* __restrict__ h0,
                                             const float* __restrict__ Whh,
                                             const float* __restrict__ bhh,
                                             float* __restrict__ outHT)
{
    __shared__ __align__(16) float hs[BB][HH];
    int tid = threadIdx.x;
    int lane = tid & 31, wid = tid >> 5;
    int j = blockIdx.x * GW + wid;
    bool valid = (j < HH);
    int c = j & 127, f = j >> 7;

    float4 wr4[8], wz4[8], wn4[8];
    float br = 0.f, bz = 0.f, bn = 0.f;
    if (valid) {
        const float* wr = Whh + (size_t)j * HH;
        const float* wz = Whh + (size_t)(j + HH) * HH;
        const float* wn = Whh + (size_t)(j + 2 * HH) * HH;
#pragma unroll
        for (int i = 0; i < 8; ++i) {
            wr4[i] = *(const float4*)&wr[i * 128 + lane * 4];
            wz4[i] = *(const float4*)&wz[i * 128 + lane * 4];
            wn4[i] = *(const float4*)&wn[i * 128 + lane * 4];
        }
        br = bhh[j]; bz = bhh[j + HH]; bn = bhh[j + 2 * HH];
    } else {
#pragma unroll
        for (int i = 0; i < 8; ++i) {
            wr4[i] = make_float4(0, 0, 0, 0);
            wz4[i] = make_float4(0, 0, 0, 0);
            wn4[i] = make_float4(0, 0, 0, 0);
        }
    }

    unsigned my_gen = 0;
    {
        int i = blockIdx.x * 224 + tid;
        if (i < BB * HH) g_h[0][i] = h0[i];
    }
    ++my_gen;
    grid_barrier(my_gen);

    for (int t = 0; t < TT; ++t) {
        const float4* hp = (const float4*)&g_h[t & 1][0];
        float* hw = &g_h[(t + 1) & 1][0];
#pragma unroll
        for (int i = 0; i < 10; ++i) {
            int idx4 = tid + i * 224;
            if (idx4 < 2048) {
                float4 v = hp[idx4];
                *(float4*)&hs[idx4 >> 8][(idx4 & 255) * 4] = v;
            }
        }
        __syncthreads();

        float xr = 0.f, xz = 0.f, xn = 0.f;
        if (valid && lane < 8) {
            const float* xgp = g_xg + (size_t)(lane * TT + t) * (3 * HH);
            xr = xgp[j]; xz = xgp[j + HH]; xn = xgp[j + 2 * HH];
        }

        float accR[8], accZ[8], accN[8];
#pragma unroll
        for (int b = 0; b < 8; ++b) { accR[b] = 0.f; accZ[b] = 0.f; accN[b] = 0.f; }

        if (valid) {
#pragma unroll
            for (int i = 0; i < 8; ++i) {
                float4 a = wr4[i], b4 = wz4[i], c4 = wn4[i];
#pragma unroll
                for (int b = 0; b < 8; ++b) {
                    float4 h4 = *(const float4*)&hs[b][i * 128 + lane * 4];
                    accR[b] = fmaf(a.x, h4.x, accR[b]);
                    accR[b] = fmaf(a.y, h4.y, accR[b]);
                    accR[b] = fmaf(a.z, h4.z, accR[b]);
                    accR[b] = fmaf(a.w, h4.w, accR[b]);
                    accZ[b] = fmaf(b4.x, h4.x, accZ[b]);
                    accZ[b] = fmaf(b4.y, h4.y, accZ[b]);
                    accZ[b] = fmaf(b4.z, h4.z, accZ[b]);
                    accZ[b] = fmaf(b4.w, h4.w, accZ[b]);
                    accN[b] = fmaf(c4.x, h4.x, accN[b]);
                    accN[b] = fmaf(c4.y, h4.y, accN[b]);
                    accN[b] = fmaf(c4.z, h4.z, accN[b]);
                    accN[b] = fmaf(c4.w, h4.w, accN[b]);
                }
            }
#pragma unroll
            for (int b = 0; b < 8; ++b)
#pragma unroll
                for (int off = 16; off; off >>= 1) {
                    accR[b] += __shfl_xor_sync(0xffffffffu, accR[b], off);
                    accZ[b] += __shfl_xor_sync(0xffffffffu, accZ[b], off);
                    accN[b] += __shfl_xor_sync(0xffffffffu, accN[b], off);
                }
            if (lane < 8) {
                int b = lane;
                float r = 1.f / (1.f + __expf(-(xr + accR[b] + br)));
                float z = 1.f / (1.f + __expf(-(xz + accZ[b] + bz)));
                float n = tanhf(xn + r * (accN[b] + bn));
                float hnew = (1.f - z) * n + z * hs[b][j];
                hw[b * HH + j] = hnew;
                g_emb2[((size_t)(b * CC + c) * TT + t) * 8 + f] = hnew;
                if (t == TT - 1) outHT[b * HH + j] = hnew;
            }
        }
        ++my_gen;
        grid_barrier(my_gen);
    }
}

// ---------------- pconv: out = W @ x + bias + skip, mma split-bf16 ------------
// M=128(oc), N=64(pos), K=128(ic); in-kernel activation split.
__global__ __launch_bounds__(256) void k_pconv_mma(float* __restrict__ out,
                                                   const float* __restrict__ in,
                                                   const unsigned short* __restrict__ Wh,
                                                   const unsigned short* __restrict__ Wl,
                                                   const float* __restrict__ bias,
                                                   const float* __restrict__ skip,
                                                   int TF)
{
    __shared__ __align__(16) unsigned short sWh[128][40];
    __shared__ __align__(16) unsigned short sWl[128][40];
    __shared__ __align__(16) unsigned short sXh[64][40];
    __shared__ __align__(16) unsigned short sXl[64][40];
    int tid = threadIdx.x, lane = tid & 31, wid = tid >> 5;
    int wm = wid >> 1, wn = wid & 1;
    int b = blockIdx.y;
    int p0 = blockIdx.x * 64;

    float acc[2][4][4];
#pragma unroll
    for (int mi = 0; mi < 2; ++mi)
#pragma unroll
        for (int ni = 0; ni < 4; ++ni)
#pragma unroll
            for (int q = 0; q < 4; ++q) acc[mi][ni][q] = 0.f;

    int icr = tid >> 3, pc = (tid & 7) * 8;   // X loader coords

    for (int kc = 0; kc < CC; kc += 32) {
        __syncthreads();
        // weights: 512 uint4 per tensor, 2 per thread
#pragma unroll
        for (int i = 0; i < 2; ++i) {
            int idx = tid + i * 256;
            int row = idx >> 2, c8 = (idx & 3) * 8;
            *(uint4*)&sWh[row][c8] = *(const uint4*)&Wh[row * CC + kc + c8];
            *(uint4*)&sWl[row][c8] = *(const uint4*)&Wl[row * CC + kc + c8];
        }
        // X: 32 ic-rows x 64 pos fp32, split + transpose to [pos][k]
        {
            const float* xp = &in[(size_t)(b * CC + kc + icr) * TF + p0 + pc];
            float4 v0 = *(const float4*)xp;
            float4 v1 = *(const float4*)(xp + 4);
            float f[8] = { v0.x, v0.y, v0.z, v0.w, v1.x, v1.y, v1.z, v1.w };
#pragma unroll
            for (int q = 0; q < 8; ++q) {
                unsigned short h, l;
                split1(f[q], h, l);
                sXh[pc + q][icr] = h;
                sXl[pc + q][icr] = l;
            }
        }
        __syncthreads();

#pragma unroll
        for (int ks = 0; ks < 2; ++ks) {
            int k0 = ks * 16;
            unsigned ah[2][4], al[2][4];
#pragma unroll
            for (int mi = 0; mi < 2; ++mi) {
                int m = wm * 32 + mi * 16 + (lane & 15);
                int kk = k0 + (lane >> 4) * 8;
                ldsm4(ah[mi], smem_u32(&sWh[m][kk]));
                ldsm4(al[mi], smem_u32(&sWl[m][kk]));
            }
            unsigned bh[4][2], bl[4][2];
#pragma unroll
            for (int ni = 0; ni < 4; ++ni) {
                int r = lane & 15;
                int n = wn * 32 + ni * 8 + (r & 7);
                int kk = k0 + (r >> 3) * 8;
                ldsm2(bh[ni], smem_u32(&sXh[n][kk]));
                ldsm2(bl[ni], smem_u32(&sXl[n][kk]));
            }
#pragma unroll
            for (int mi = 0; mi < 2; ++mi)
#pragma unroll
                for (int ni = 0; ni < 4; ++ni) {
                    mma16816(acc[mi][ni], ah[mi], bh[ni]);
                    mma16816(acc[mi][ni], ah[mi], bl[ni]);
                    mma16816(acc[mi][ni], al[mi], bh[ni]);
                }
        }
    }
    int gr = lane >> 2, gc = (lane & 3) * 2;
#pragma unroll
    for (int mi = 0; mi < 2; ++mi)
#pragma unroll
        for (int ni = 0; ni < 4; ++ni) {
            int oc = wm * 32 + mi * 16 + gr;
            int p = p0 + wn * 32 + ni * 8 + gc;
            size_t i0 = (size_t)(b * CC + oc) * TF + p;
            float bv = bias[oc];
            float2 s0 = *(const float2*)&skip[i0];
            float2 v0 = { acc[mi][ni][0] + bv + s0.x, acc[mi][ni][1] + bv + s0.y };
            *(float2*)&out[i0] = v0;
            int oc2 = oc + 8;
            size_t i2 = (size_t)(b * CC + oc2) * TF + p;
            float bv2 = bias[oc2];
            float2 s2 = *(const float2*)&skip[i2];
            float2 v1 = { acc[mi][ni][2] + bv2 + s2.x, acc[mi][ni][3] + bv2 + s2.y };
            *(float2*)&out[i2] = v1;
        }
}

// ---------------- convt (k=3, s=2 over freq) + ReLU, mma split-bf16 -----------
// Wh/Wl: [tap][oc][ic]. Block: 32 input positions, all 128 oc. K-chunk 16.
__global__ __launch_bounds__(256) void k_convt_mma(float* __restrict__ out,
                                                   const float* __restrict__ in,
                                                   const unsigned short* __restrict__ Wh,
                                                   const unsigned short* __restrict__ Wl,
                                                   const float* __restrict__ bias,
                                                   int Fin, int TF)
{
    __shared__ __align__(16) unsigned short sW[6][128][24]; // [tap*2 + (0=h,1=l)]
    __shared__ __align__(16) unsigned short sXh[32][24];
    __shared__ __align__(16) unsigned short sXl[32][24];
    __shared__ __align__(16) unsigned short sYh[32][24];
    __shared__ __align__(16) unsigned short sYl[32][24];
    int tid = threadIdx.x, lane = tid & 31, wid = tid >> 5;
    int wm = wid >> 1, wn = wid & 1;
    int b = blockIdx.y;
    int p0 = blockIdx.x * 32;

    float ae[2][2][4], ao[2][2][4];
#pragma unroll
    for (int mi = 0; mi < 2; ++mi)
#pragma unroll
        for (int ni = 0; ni < 2; ++ni)
#pragma unroll
            for (int q = 0; q < 4; ++q) { ae[mi][ni][q] = 0.f; ao[mi][ni][q] = 0.f; }

    int icr = tid >> 4, pc = (tid & 15) * 2;   // X loader: 16 rows x 32 pos

    for (int kc = 0; kc < CC; kc += 16) {
        __syncthreads();
        // 6 weight tiles: 256 uint4 each, 6 per thread
#pragma unroll
        for (int i = 0; i < 6; ++i) {
            int idx = tid + i * 256;
            int tile = idx >> 8, rem = idx & 255;
            int row = rem >> 1, c8 = (rem & 1) * 8;
            int tap = tile >> 1;
            const unsigned short* src = ((tile & 1) ? Wl : Wh)
                + (size_t)tap * (CC * CC) + row * CC + kc + c8;
            *(uint4*)&sW[tile][row][c8] = *(const uint4*)src;
        }
        // X: 16 ic-rows x 32 pos, split + transpose
        {
            float2 v = *(const float2*)&in[(size_t)(b * CC + kc + icr) * TF + p0 + pc];
            unsigned short h, l;
            split1(v.x, h, l); sXh[pc][icr] = h; sXl[pc][icr] = l;
            split1(v.y, h, l); sXh[pc + 1][icr] = h; sXl[pc + 1][icr] = l;
        }
        __syncthreads();
        // shifted tile Y[p] = (p not at freq boundary) ? X[p+1] : 0
        {
#pragma unroll
            for (int q = 0; q < 2; ++q) {
                int p = pc + q;
                bool ok = ((p & (Fin - 1)) != (Fin - 1));
                sYh[p][icr] = ok ? sXh[p + 1][icr] : (unsigned short)0;
                sYl[p][icr] = ok ? sXl[p + 1][icr] : (unsigned short)0;
            }
        }
        __syncthreads();

        // B fragments (K=16: single k-step)
        unsigned bxh[2][2], bxl[2][2], byh[2][2], byl[2][2];
#pragma unroll
        for (int ni = 0; ni < 2; ++ni) {
            int r = lane & 15;
            int n = wn * 16 + ni * 8 + (r & 7);
            int kk = (r >> 3) * 8;
            ldsm2(bxh[ni], smem_u32(&sXh[n][kk]));
            ldsm2(bxl[ni], smem_u32(&sXl[n][kk]));
            ldsm2(byh[ni], smem_u32(&sYh[n][kk]));
            ldsm2(byl[ni], smem_u32(&sYl[n][kk]));
        }
        int mrow = wm * 32 + (lane & 15);
        int mkk = (lane >> 4) * 8;
        unsigned ah[2][4], al[2][4];
        // tap1 -> even
#pragma unroll
        for (int mi = 0; mi < 2; ++mi) {
            ldsm4(ah[mi], smem_u32(&sW[2][mrow + mi * 16][mkk]));
            ldsm4(al[mi], smem_u32(&sW[3][mrow + mi * 16][mkk]));
        }
#pragma unroll
        for (int mi = 0; mi < 2; ++mi)
#pragma unroll
            for (int ni = 0; ni < 2; ++ni) {
                mma16816(ae[mi][ni], ah[mi], bxh[ni]);
                mma16816(ae[mi][ni], ah[mi], bxl[ni]);
                mma16816(ae[mi][ni], al[mi], bxh[ni]);
            }
        // tap0 -> odd (X)
#pragma unroll
        for (int mi = 0; mi < 2; ++mi) {
            ldsm4(ah[mi], smem_u32(&sW[0][mrow + mi * 16][mkk]));
            ldsm4(al[mi], smem_u32(&sW[1][mrow + mi * 16][mkk]));
        }
#pragma unroll
        for (int mi = 0; mi < 2; ++mi)
#pragma unroll
            for (int ni = 0; ni < 2; ++ni) {
                mma16816(ao[mi][ni], ah[mi], bxh[ni]);
                mma16816(ao[mi][ni], ah[mi], bxl[ni]);
                mma16816(ao[mi][ni], al[mi], bxh[ni]);
            }
        // tap2 -> odd (Y)
#pragma unroll
        for (int mi = 0; mi < 2; ++mi) {
            ldsm4(ah[mi], smem_u32(&sW[4][mrow + mi * 16][mkk]));
            ldsm4(al[mi], smem_u32(&sW[5][mrow + mi * 16][mkk]));
        }
#pragma unroll
        for (int mi = 0; mi < 2; ++mi)
#pragma unroll
            for (int ni = 0; ni < 2; ++ni) {
                mma16816(ao[mi][ni], ah[mi], byh[ni]);
                mma16816(ao[mi][ni], ah[mi], byl[ni]);
                mma16816(ao[mi][ni], al[mi], byh[ni]);
            }
    }
    int TF2 = TF * 2;
    int gr = lane >> 2, gc = (lane & 3) * 2;
#pragma unroll
    for (int mi = 0; mi < 2; ++mi)
#pragma unroll
        for (int ni = 0; ni < 2; ++ni) {
            int oc = wm * 32 + mi * 16 + gr;
            int pin = p0 + wn * 16 + ni * 8 + gc;
            float bv = bias[oc];
            float4 o;
            o.x = fmaxf(ae[mi][ni][0] + bv, 0.f);
            o.y = fmaxf(ao[mi][ni][0] + bv, 0.f);
            o.z = fmaxf(ae[mi][ni][1] + bv, 0.f);
            o.w = fmaxf(ao[mi][ni][1] + bv, 0.f);
            *(float4*)&out[(size_t)(b * CC + oc) * TF2 + 2 * pin] = o;
            int oc2 = oc + 8;
            float bv2 = bias[oc2];
            float4 o2;
            o2.x = fmaxf(ae[mi][ni][2] + bv2, 0.f);
            o2.y = fmaxf(ao[mi][ni][2] + bv2, 0.f);
            o2.z = fmaxf(ae[mi][ni][3] + bv2, 0.f);
            o2.w = fmaxf(ao[mi][ni][3] + bv2, 0.f);
            *(float4*)&out[(size_t)(b * CC + oc2) * TF2 + 2 * pin] = o2;
        }
}

// ---------------- final: mma GEMM + e1x skip + k3 freq conv + sigmoid ---------
__global__ __launch_bounds__(256) void k_final_mma(const float* __restrict__ e0,
                                                   const unsigned short* __restrict__ Wh,
                                                   const unsigned short* __restrict__ Wl,
                                                   const float* __restrict__ bias,
                                                   const float* __restrict__ w0o,
                                                   const float* __restrict__ b0o,
                                                   float* __restrict__ outm)
{
    __shared__ __align__(16) union U {
        struct {
            unsigned short Wh[128][40];
            unsigned short Wl[128][40];
            unsigned short Xh[64][40];
            unsigned short Xl[64][40];
        } g;
        float pre[128][64];
    } u;
    __shared__ float wo[128][3];
    const int TF = TT * 64;
    int tid = threadIdx.x, lane = tid & 31, wid = tid >> 5;
    int wm = wid >> 1, wn = wid & 1;
    int b = blockIdx.y, t = blockIdx.x;
    int p0 = t * 64;

    for (int i = tid; i < 384; i += 256) wo[i / 3][i % 3] = w0o[i];

    float acc[2][4][4];
#pragma unroll
    for (int mi = 0; mi < 2; ++mi)
#pragma unroll
        for (int ni = 0; ni < 4; ++ni)
#pragma unroll
            for (int q = 0; q < 4; ++q) acc[mi][ni][q] = 0.f;

    int icr = tid >> 3, pc = (tid & 7) * 8;

    for (int kc = 0; kc < CC; kc += 32) {
        __syncthreads();
#pragma unroll
        for (int i = 0; i < 2; ++i) {
            int idx = tid + i * 256;
            int row = idx >> 2, c8 = (idx & 3) * 8;
            *(uint4*)&u.g.Wh[row][c8] = *(const uint4*)&Wh[row * CC + kc + c8];
            *(uint4*)&u.g.Wl[row][c8] = *(const uint4*)&Wl[row * CC + kc + c8];
        }
        {
            const float* xp = &e0[(size_t)(b * CC + kc + icr) * TF + p0 + pc];
            float4 v0 = *(const float4*)xp;
            float4 v1 = *(const float4*)(xp + 4);
            float f[8] = { v0.x, v0.y, v0.z, v0.w, v1.x, v1.y, v1.z, v1.w };
#pragma unroll
            for (int q = 0; q < 8; ++q) {
                unsigned short h, l;
                split1(f[q], h, l);
                u.g.Xh[pc + q][icr] = h;
                u.g.Xl[pc + q][icr] = l;
            }
        }
        __syncthreads();

#pragma unroll
        for (int ks = 0; ks < 2; ++ks) {
            int k0 = ks * 16;
            unsigned ah[2][4], al[2][4];
#pragma unroll
            for (int mi = 0; mi < 2; ++mi) {
                int m = wm * 32 + mi * 16 + (lane & 15);
                int kk = k0 + (lane >> 4) * 8;
                ldsm4(ah[mi], smem_u32(&u.g.Wh[m][kk]));
                ldsm4(al[mi], smem_u32(&u.g.Wl[m][kk]));
            }
            unsigned bh[4][2], bl[4][2];
#pragma unroll
            for (int ni = 0; ni < 4; ++ni) {
                int r = lane & 15;
                int n = wn * 32 + ni * 8 + (r & 7);
                int kk = k0 + (r >> 3) * 8;
                ldsm2(bh[ni], smem_u32(&u.g.Xh[n][kk]));
                ldsm2(bl[ni], smem_u32(&u.g.Xl[n][kk]));
            }
#pragma unroll
            for (int mi = 0; mi < 2; ++mi)
#pragma unroll
                for (int ni = 0; ni < 4; ++ni) {
                    mma16816(acc[mi][ni], ah[mi], bh[ni]);
                    mma16816(acc[mi][ni], ah[mi], bl[ni]);
                    mma16816(acc[mi][ni], al[mi], bh[ni]);
                }
        }
    }
    __syncthreads();   // all warps done reading u.g before overwriting with pre
    int gr = lane >> 2, gc = (lane & 3) * 2;
#pragma unroll
    for (int mi = 0; mi < 2; ++mi)
#pragma unroll
        for (int ni = 0; ni < 4; ++ni) {
            int oc = wm * 32 + mi * 16 + gr;
            int p = wn * 32 + ni * 8 + gc;
            size_t i0 = (size_t)(b * CC + oc) * TF + p0 + p;
            float bv = bias[oc];
            u.pre[oc][p]     = acc[mi][ni][0] + bv + g_e1x[i0];
            u.pre[oc][p + 1] = acc[mi][ni][1] + bv + g_e1x[i0 + 1];
            int oc2 = oc + 8;
            size_t i2 = (size_t)(b * CC + oc2) * TF + p0 + p;
            float bv2 = bias[oc2];
            u.pre[oc2][p]     = acc[mi][ni][2] + bv2 + g_e1x[i2];
            u.pre[oc2][p + 1] = acc[mi][ni][3] + bv2 + g_e1x[i2 + 1];
        }
    __syncthreads();
    int f = tid >> 2, q = tid & 3;
    float s = 0.f;
#pragma unroll 4
    for (int i = 0; i < 32; ++i) {
        int ch = q * 32 + i;
        float x0 = u.pre[ch][f];
        float xm = (f > 0) ? u.pre[ch][f - 1] : 0.f;
        float xp = (f < 63) ? u.pre[ch][f + 1] : 0.f;
        s = fmaf(wo[ch][0], xm, s);
        s = fmaf(wo[ch][1], x0, s);
        s = fmaf(wo[ch][2], xp, s);
    }
    s += __shfl_down_sync(0xffffffffu, s, 1);
    s += __shfl_down_sync(0xffffffffu, s, 2);
    if (q == 0) outm[((size_t)b * TT + t) * 64 + f] = 1.f / (1.f + __expf(-(s + b0o[0])));
}

// ---------------------------------- launch ----------------------------------
extern "C" void kernel_launch(void* const* d_in, const int* in_sizes, int n_in,
                              void* d_out, int out_size)
{
    const float* emb   = (const float*)d_in[0];
    const float* e3    = (const float*)d_in[1];
    const float* e2    = (const float*)d_in[2];
    const float* e1    = (const float*)d_in[3];
    const float* e0    = (const float*)d_in[4];
    const float* h_erb = (const float*)d_in[5];
    const float* Wih   = (const float*)d_in[6];
    const float* Whh   = (const float*)d_in[7];
    const float* bih   = (const float*)d_in[8];
    const float* bhh   = (const float*)d_in[9];
    const float* w3p   = (const float*)d_in[10];
    const float* b3p   = (const float*)d_in[11];
    const float* w2p   = (const float*)d_in[12];
    const float* b2p   = (const float*)d_in[13];
    const float* w1p   = (const float*)d_in[14];
    const float* b1p   = (const float*)d_in[15];
    const float* w0p   = (const float*)d_in[16];
    const float* b0p   = (const float*)d_in[17];
    const float* wt3   = (const float*)d_in[18];
    const float* bt3   = (const float*)d_in[19];
    const float* wt2   = (const float*)d_in[20];
    const float* bt2   = (const float*)d_in[21];
    const float* wt1   = (const float*)d_in[22];
    const float* bt1   = (const float*)d_in[23];
    const float* w0o   = (const float*)d_in[24];
    const float* b0o   = (const float*)d_in[25];
    float* out = (float*)d_out;

    float* gx3;  cudaGetSymbolAddress((void**)&gx3,  g_x3);
    float* ge3x; cudaGetSymbolAddress((void**)&ge3x, g_e3x);
    float* gx2;  cudaGetSymbolAddress((void**)&gx2,  g_x2);
    float* ge2x; cudaGetSymbolAddress((void**)&ge2x, g_e2x);
    float* gx1;  cudaGetSymbolAddress((void**)&gx1,  g_x1);
    float* ge1x; cudaGetSymbolAddress((void**)&ge1x, g_e1x);
    float* gemb2;cudaGetSymbolAddress((void**)&gemb2,g_emb2);
    void *pAh, *pAl, *pWh, *pWl, *ppwh, *ppwl, *pcwh, *pcwl;
    cudaGetSymbolAddress(&pAh, g_Ah);
    cudaGetSymbolAddress(&pAl, g_Al);
    cudaGetSymbolAddress(&pWh, g_Wh);
    cudaGetSymbolAddress(&pWl, g_Wl);
    cudaGetSymbolAddress(&ppwh, g_pwh);
    cudaGetSymbolAddress(&ppwl, g_pwl);
    cudaGetSymbolAddress(&pcwh, g_cwh);
    cudaGetSymbolAddress(&pcwl, g_cwl);
    unsigned short* pwh = (unsigned short*)ppwh;
    unsigned short* pwl = (unsigned short*)ppwl;
    unsigned short* cwh = (unsigned short*)pcwh;
    unsigned short* cwl = (unsigned short*)pcwl;

    // launch order chosen so ncu (-s 5 -c 1) profiles k_gru (index 5)
    k_split<<<4096, 256>>>((const float4*)emb,
                           (ushort4*)pAh, (ushort4*)pAl, 1048576);  // 0
    k_split<<<3072, 256>>>((const float4*)Wih,
                           (ushort4*)pWh, (ushort4*)pWl, 786432);   // 1
    k_xg_mma<<<dim3(48, 32), 256>>>(bih);                           // 2
    k_split_pw<<<256, 256>>>(w3p, w2p, w1p, w0p);                   // 3
    k_reset<<<1, 32>>>();                                           // 4
    k_gru<<<GBLK, 224>>>(h_erb, Whh, bhh, out + BB * TT * 64);      // 5
    k_split_cw<<<576, 256>>>(wt3, wt2, wt1);                        // 6

    k_pconv_mma<<<dim3(64, 8),  256>>>(gx3, e3, pwh, pwl, b3p, gemb2, TT * 8);
    k_convt_mma<<<dim3(128, 8), 256>>>(ge3x, gx3, cwh, cwl, bt3, 8, TT * 8);

    k_pconv_mma<<<dim3(128, 8), 256>>>(gx2, e2, pwh + 16384, pwl + 16384, b2p, ge3x, TT * 16);
    k_convt_mma<<<dim3(256, 8), 256>>>(ge2x, gx2, cwh + 49152, cwl + 49152, bt2, 16, TT * 16);

    k_pconv_mma<<<dim3(256, 8), 256>>>(gx1, e1, pwh + 32768, pwl + 32768, b1p, ge2x, TT * 32);
    k_convt_mma<<<dim3(512, 8), 256>>>(ge1x, gx1, cwh + 98304, cwl + 98304, bt1, 32, TT * 32);

    k_final_mma<<<dim3(512, 8), 256>>>(e0, pwh + 49152, pwl + 49152, b0p, w0o, b0o, out);
}

// round 11
// speedup vs baseline: 1.1609x; 1.1609x over previous
#include <cuda_runtime.h>
#include <cuda_bf16.h>

#define BB 8
#define TT 512
#define CC 128
#define HH 1024
#define GBLK 148
#define GW 7

typedef unsigned long long ull;
typedef unsigned short ushort_t;

// ---------------- f32x2 helpers (decoder kernels) ----------------
__device__ __forceinline__ ull dup2(float x)
{
    ull r;
    asm("mov.b64 %0, {%1, %1};" : "=l"(r) : "f"(x));
    return r;
}
__device__ __forceinline__ ull ffma2(ull a, ull b, ull c)
{
    ull d;
    asm("fma.rn.f32x2 %0, %1, %2, %3;" : "=l"(d) : "l"(a), "l"(b), "l"(c));
    return d;
}
__device__ __forceinline__ float2 unpk2(ull v)
{
    float2 f;
    asm("mov.b64 {%0, %1}, %2;" : "=f"(f.x), "=f"(f.y) : "l"(v));
    return f;
}

// ---------------- static scratch ----------------
__device__ float g_xg[BB * TT * 3 * HH];
__device__ float g_h[2][BB * HH];
__device__ float g_emb2[BB * CC * TT * 8];
__device__ float g_x3[BB * CC * TT * 8];
__device__ float g_e3x[BB * CC * TT * 16];
__device__ float g_x2[BB * CC * TT * 16];
__device__ float g_e2x[BB * CC * TT * 32];
__device__ float g_x1[BB * CC * TT * 32];
__device__ float g_e1x[BB * CC * TT * 64];
__device__ float g_wtT3[3 * CC * CC];
__device__ float g_wtT2[3 * CC * CC];
__device__ float g_wtT1[3 * CC * CC];
__device__ unsigned short g_Ah[BB * TT * HH];
__device__ unsigned short g_Al[BB * TT * HH];
__device__ unsigned short g_Wh[3 * HH * HH];
__device__ unsigned short g_Wl[3 * HH * HH];
__device__ unsigned g_bar_count;
__device__ unsigned g_bar_gen;

// ---------------- barrier state reset (per launch) ----------------
__global__ void k_reset()
{
    if (threadIdx.x == 0) { g_bar_count = 0; g_bar_gen = 0; }
}

// ---------------- acquire/release grid barrier ----------------
__device__ __forceinline__ void grid_barrier(unsigned my_gen)
{
    __syncthreads();
    if (threadIdx.x == 0) {
        unsigned arr;
        asm volatile("atom.add.release.gpu.u32 %0, [%1], 1;"
                     : "=r"(arr) : "l"(&g_bar_count) : "memory");
        if (arr == GBLK - 1) {
            g_bar_count = 0;
            asm volatile("st.release.gpu.u32 [%0], %1;"
                         :: "l"(&g_bar_gen), "r"(my_gen) : "memory");
        } else {
            unsigned cur;
            do {
                asm volatile("ld.acquire.gpu.u32 %0, [%1];"
                             : "=r"(cur) : "l"(&g_bar_gen) : "memory");
            } while ((int)(cur - my_gen) < 0);
        }
    }
    __syncthreads();
}

// ---------------- splitting helper ----------------
__device__ __forceinline__ void split1(float v, unsigned short& h, unsigned short& l)
{
    __nv_bfloat16 bh = __float2bfloat16(v);
    float r = v - __bfloat162float(bh);
    __nv_bfloat16 bl = __float2bfloat16(r);
    h = *(unsigned short*)&bh;
    l = *(unsigned short*)&bl;
}

// ---------------- bf16 hi/lo split: fp32 tensor -> (hi, lo) ----------------
__global__ __launch_bounds__(256) void k_split(const float4* __restrict__ src,
                                               ushort4* __restrict__ hi,
                                               ushort4* __restrict__ lo,
                                               int n4)
{
    int i = blockIdx.x * 256 + threadIdx.x;
    if (i >= n4) return;
    float4 v = src[i];
    float f[4] = { v.x, v.y, v.z, v.w };
    unsigned short h[4], l[4];
#pragma unroll
    for (int q = 0; q < 4; ++q) split1(f[q], h[q], l[q]);
    hi[i] = make_ushort4(h[0], h[1], h[2], h[3]);
    lo[i] = make_ushort4(l[0], l[1], l[2], l[3]);
}

// ---------------- mma helpers (sm_80-baseline PTX) ----------------
__device__ __forceinline__ unsigned smem_u32(const void* p)
{
    unsigned a;
    asm("{ .reg .u64 t; cvta.to.shared.u64 t, %1; cvt.u32.u64 %0, t; }"
        : "=r"(a) : "l"(p));
    return a;
}
__device__ __forceinline__ void ldsm4(unsigned* r, unsigned addr)
{
    asm volatile("ldmatrix.sync.aligned.m8n8.x4.shared.b16 {%0,%1,%2,%3}, [%4];"
        : "=r"(r[0]), "=r"(r[1]), "=r"(r[2]), "=r"(r[3]) : "r"(addr));
}
__device__ __forceinline__ void ldsm2(unsigned* r, unsigned addr)
{
    asm volatile("ldmatrix.sync.aligned.m8n8.x2.shared.b16 {%0,%1}, [%2];"
        : "=r"(r[0]), "=r"(r[1]) : "r"(addr));
}
__device__ __forceinline__ void mma16816(float* d, const unsigned* a, const unsigned* b)
{
    asm volatile("mma.sync.aligned.m16n8k16.row.col.f32.bf16.bf16.f32 "
        "{%0,%1,%2,%3}, {%4,%5,%6,%7}, {%8,%9}, {%0,%1,%2,%3};"
        : "+f"(d[0]), "+f"(d[1]), "+f"(d[2]), "+f"(d[3])
        : "r"(a[0]), "r"(a[1]), "r"(a[2]), "r"(a[3]), "r"(b[0]), "r"(b[1]));
}

// ---------------- xg = emb @ Wih^T + bih : mma.sync split-bf16 ----------------
__global__ __launch_bounds__(256) void k_xg_mma(const float* __restrict__ bias)
{
    __shared__ __align__(16) unsigned short sAh[128][40];
    __shared__ __align__(16) unsigned short sAl[128][40];
    __shared__ __align__(16) unsigned short sWh[64][40];
    __shared__ __align__(16) unsigned short sWl[64][40];
    int tid = threadIdx.x, lane = tid & 31, wid = tid >> 5;
    int wm = wid >> 1, wn = wid & 1;
    int m0 = blockIdx.y * 128, n0 = blockIdx.x * 64;

    float acc[2][4][4];
#pragma unroll
    for (int mi = 0; mi < 2; ++mi)
#pragma unroll
        for (int ni = 0; ni < 4; ++ni)
#pragma unroll
            for (int q = 0; q < 4; ++q) acc[mi][ni][q] = 0.f;

    for (int kc = 0; kc < HH; kc += 32) {
        __syncthreads();
#pragma unroll
        for (int i = 0; i < 6; ++i) {
            int idx = tid + i * 256;
            const uint4* src;
            unsigned short* dst;
            if (idx < 512) {
                int row = idx >> 2, c8 = (idx & 3) * 8;
                src = (const uint4*)&g_Ah[(size_t)(m0 + row) * HH + kc + c8];
                dst = &sAh[row][c8];
            } else if (idx < 1024) {
                int e = idx - 512;
                int row = e >> 2, c8 = (e & 3) * 8;
                src = (const uint4*)&g_Al[(size_t)(m0 + row) * HH + kc + c8];
                dst = &sAl[row][c8];
            } else if (idx < 1280) {
                int e = idx - 1024;
                int row = e >> 2, c8 = (e & 3) * 8;
                src = (const uint4*)&g_Wh[(size_t)(n0 + row) * HH + kc + c8];
                dst = &sWh[row][c8];
            } else {
                int e = idx - 1280;
                int row = e >> 2, c8 = (e & 3) * 8;
                src = (const uint4*)&g_Wl[(size_t)(n0 + row) * HH + kc + c8];
                dst = &sWl[row][c8];
            }
            *(uint4*)dst = *src;
        }
        __syncthreads();

#pragma unroll
        for (int ks = 0; ks < 2; ++ks) {
            int k0 = ks * 16;
            unsigned ah[2][4], al[2][4];
#pragma unroll
            for (int mi = 0; mi < 2; ++mi) {
                int m = wm * 32 + mi * 16 + (lane & 15);
                int kk = k0 + (lane >> 4) * 8;
                ldsm4(ah[mi], smem_u32(&sAh[m][kk]));
                ldsm4(al[mi], smem_u32(&sAl[m][kk]));
            }
            unsigned bh[4][2], bl[4][2];
#pragma unroll
            for (int ni = 0; ni < 4; ++ni) {
                int r = lane & 15;
                int n = wn * 32 + ni * 8 + (r & 7);
                int kk = k0 + (r >> 3) * 8;
                ldsm2(bh[ni], smem_u32(&sWh[n][kk]));
                ldsm2(bl[ni], smem_u32(&sWl[n][kk]));
            }
#pragma unroll
            for (int mi = 0; mi < 2; ++mi)
#pragma unroll
                for (int ni = 0; ni < 4; ++ni) {
                    mma16816(acc[mi][ni], ah[mi], bh[ni]);
                    mma16816(acc[mi][ni], ah[mi], bl[ni]);
                    mma16816(acc[mi][ni], al[mi], bh[ni]);
                }
        }
    }
    int gr = lane >> 2, gc = (lane & 3) * 2;
#pragma unroll
    for (int mi = 0; mi < 2; ++mi)
#pragma unroll
        for (int ni = 0; ni < 4; ++ni) {
            int m = m0 + wm * 32 + mi * 16 + gr;
            int n = n0 + wn * 32 + ni * 8 + gc;
            float b0 = bias[n], b1 = bias[n + 1];
            float2 v0 = { acc[mi][ni][0] + b0, acc[mi][ni][1] + b1 };
            float2 v1 = { acc[mi][ni][2] + b0, acc[mi][ni][3] + b1 };
            *(float2*)&g_xg[(size_t)m * (3 * HH) + n] = v0;
            *(float2*)&g_xg[(size_t)(m + 8) * (3 * HH) + n] = v1;
        }
}

// ---------------- persistent GRU via mma.sync split-bf16 ----------------
// Block owns 7 hidden units -> 21 weight rows (unit*3+gate), padded to 32.
// Weights resident in dynamic smem (split-bf16). 8 warps, each a K=128 slice.
#define GRU_STRIDE 1032
#define OFF_WH 0
#define OFF_WL 66048
#define OFF_HH 132096
#define OFF_HL 148608
#define OFF_RED 165120
#define OFF_G 173312
#define GRU_SMEM 174336

__global__ __launch_bounds__(256) void k_gru(const float* __restrict__ h0,
                                             const float* __restrict__ Whh,
                                             const float* __restrict__ bhh,
                                             float* __restrict__ outHT)
{
    extern __shared__ char gsm[];
    ushort_t (*sWh)[GRU_STRIDE] = (ushort_t(*)[GRU_STRIDE])(gsm + OFF_WH);
    ushort_t (*sWl)[GRU_STRIDE] = (ushort_t(*)[GRU_STRIDE])(gsm + OFF_WL);
    ushort_t (*sHh)[GRU_STRIDE] = (ushort_t(*)[GRU_STRIDE])(gsm + OFF_HH);
    ushort_t (*sHl)[GRU_STRIDE] = (ushort_t(*)[GRU_STRIDE])(gsm + OFF_HL);
    float (*sRed)[32][8] = (float(*)[32][8])(gsm + OFF_RED);
    float (*sG)[8] = (float(*)[8])(gsm + OFF_G);

    int tid = threadIdx.x, lane = tid & 31, wid = tid >> 5;

    // epilogue thread mapping (tid < 56): unit = tid>>3, batch = tid&7
    int eu = tid >> 3, eb = tid & 7;
    int ej = blockIdx.x * GW + eu;
    bool epv = (tid < 56) && (ej < HH);
    float br_ = 0.f, bz_ = 0.f, bn_ = 0.f;
    int ec = ej & 127, ef = ej >> 7;
    if (epv) { br_ = bhh[ej]; bz_ = bhh[ej + HH]; bn_ = bhh[ej + 2 * HH]; }

    // preload weights (split fp32 -> bf16 hi/lo), rows = unit*3+gate, pad to 32
    for (int idx = tid; idx < 32 * HH; idx += 256) {
        int row = idx >> 10, k = idx & 1023;
        float v = 0.f;
        if (row < 21) {
            int unit = row / 3, gate = row - unit * 3;
            int j = blockIdx.x * GW + unit;
            if (j < HH) v = Whh[(size_t)(j + gate * HH) * HH + k];
        }
        unsigned short h, l;
        split1(v, h, l);
        sWh[row][k] = h;
        sWl[row][k] = l;
    }

    unsigned my_gen = 0;
    {
        int i = blockIdx.x * 256 + tid;
        if (i < BB * HH) g_h[0][i] = h0[i];
    }
    ++my_gen;
    grid_barrier(my_gen);

    int kbase = wid * 128;

    for (int t = 0; t < TT; ++t) {
        // prefetch epilogue inputs (xg independent of current h; g_h stable this step)
        float xr = 0.f, xz = 0.f, xn = 0.f, hprev = 0.f;
        if (epv) {
            const float* xgp = g_xg + ((size_t)eb * TT + t) * (3 * HH);
            xr = xgp[ej]; xz = xgp[ej + HH]; xn = xgp[ej + 2 * HH];
            hprev = g_h[t & 1][eb * HH + ej];
        }
        // split h -> smem bf16 hi/lo
        const float4* hp = (const float4*)&g_h[t & 1][0];
#pragma unroll
        for (int i = 0; i < 8; ++i) {
            int idx4 = tid + i * 256;            // 0..2047
            float4 v = hp[idx4];
            int b = idx4 >> 8, k4 = (idx4 & 255) * 4;
            unsigned short h0_, l0_, h1_, l1_, h2_, l2_, h3_, l3_;
            split1(v.x, h0_, l0_);
            split1(v.y, h1_, l1_);
            split1(v.z, h2_, l2_);
            split1(v.w, h3_, l3_);
            *(ushort4*)&sHh[b][k4] = make_ushort4(h0_, h1_, h2_, h3_);
            *(ushort4*)&sHl[b][k4] = make_ushort4(l0_, l1_, l2_, l3_);
        }
        __syncthreads();

        // mma over this warp's K slice (3 accumulator sets to shorten chains)
        float a0[2][4], a1[2][4], a2[2][4];
#pragma unroll
        for (int mi = 0; mi < 2; ++mi)
#pragma unroll
            for (int q = 0; q < 4; ++q) { a0[mi][q] = 0.f; a1[mi][q] = 0.f; a2[mi][q] = 0.f; }

#pragma unroll
        for (int ks = 0; ks < 8; ++ks) {
            int kk = kbase + ks * 16;
            unsigned bh[2], bl[2];
            int r = lane & 15;
            ldsm2(bh, smem_u32(&sHh[r & 7][kk + (r >> 3) * 8]));
            ldsm2(bl, smem_u32(&sHl[r & 7][kk + (r >> 3) * 8]));
            unsigned ah[2][4], al[2][4];
#pragma unroll
            for (int mi = 0; mi < 2; ++mi) {
                int m = mi * 16 + (lane & 15);
                int kko = kk + (lane >> 4) * 8;
                ldsm4(ah[mi], smem_u32(&sWh[m][kko]));
                ldsm4(al[mi], smem_u32(&sWl[m][kko]));
            }
#pragma unroll
            for (int mi = 0; mi < 2; ++mi) {
                mma16816(a0[mi], ah[mi], bh);
                mma16816(a1[mi], ah[mi], bl);
                mma16816(a2[mi], al[mi], bh);
            }
        }
        // store partials
        int gr = lane >> 2, gc = (lane & 3) * 2;
#pragma unroll
        for (int mi = 0; mi < 2; ++mi) {
            sRed[wid][mi * 16 + gr][gc]         = a0[mi][0] + a1[mi][0] + a2[mi][0];
            sRed[wid][mi * 16 + gr][gc + 1]     = a0[mi][1] + a1[mi][1] + a2[mi][1];
            sRed[wid][mi * 16 + gr + 8][gc]     = a0[mi][2] + a1[mi][2] + a2[mi][2];
            sRed[wid][mi * 16 + gr + 8][gc + 1] = a0[mi][3] + a1[mi][3] + a2[mi][3];
        }
        __syncthreads();
        // cross-warp reduce: 256 threads, one (row, batch) each
        {
            int row = tid >> 3, col = tid & 7;
            float s = 0.f;
#pragma unroll
            for (int w = 0; w < 8; ++w) s += sRed[w][row][col];
            sG[row][col] = s;
        }
        __syncthreads();
        // epilogue
        if (epv) {
            float sr = sG[eu * 3 + 0][eb];
            float sz = sG[eu * 3 + 1][eb];
            float sn = sG[eu * 3 + 2][eb];
            float r = 1.f / (1.f + __expf(-(xr + sr + br_)));
            float z = 1.f / (1.f + __expf(-(xz + sz + bz_)));
            float n = tanhf(xn + r * (sn + bn_));
            float hnew = (1.f - z) * n + z * hprev;
            g_h[(t + 1) & 1][eb * HH + ej] = hnew;
            g_emb2[((size_t)(eb * CC + ec) * TT + t) * 8 + ef] = hnew;
            if (t == TT - 1) outHT[eb * HH + ej] = hnew;
        }
        ++my_gen;
        grid_barrier(my_gen);
    }
}

// ---------------- 1x1 conv over channels + bias + skip, f32x2 ----------------
__global__ __launch_bounds__(256) void k_pconv(float* __restrict__ out,
                                               const float* __restrict__ in,
                                               const float* __restrict__ W,
                                               const float* __restrict__ bias,
                                               const float* __restrict__ skip,
                                               int TF)
{
    __shared__ __align__(16) float Xs[128][64];
    __shared__ __align__(16) float Ws[16][128];
    int tid = threadIdx.x;
    int tx = tid & 15, ty = tid >> 4;
    int b = blockIdx.y;
    int p0 = blockIdx.x * 64;

#pragma unroll
    for (int i = 0; i < 8; ++i) {
        int e4 = tid + i * 256;
        int ch = e4 >> 4, pq = (e4 & 15) << 2;
        *(float4*)&Xs[ch][pq] = *(const float4*)&in[(size_t)(b * CC + ch) * TF + p0 + pq];
    }
    ull acc2[4][4];
#pragma unroll
    for (int p = 0; p < 4; ++p)
#pragma unroll
        for (int q = 0; q < 4; ++q) acc2[p][q] = 0ull;

    for (int kb = 0; kb < CC; kb += 16) {
#pragma unroll
        for (int i = 0; i < 2; ++i) {
            int e4 = tid * 2 + i;
            int oc = e4 >> 2, k4 = (e4 & 3) << 2;
            float4 v = *(const float4*)&W[oc * CC + kb + k4];
            Ws[k4 + 0][oc] = v.x; Ws[k4 + 1][oc] = v.y;
            Ws[k4 + 2][oc] = v.z; Ws[k4 + 3][oc] = v.w;
        }
        __syncthreads();
#pragma unroll
        for (int kk = 0; kk < 16; ++kk) {
            float4 xv = *(const float4*)&Xs[kb + kk][tx * 4];
            ull dx[4];
            dx[0] = dup2(xv.x); dx[1] = dup2(xv.y);
            dx[2] = dup2(xv.z); dx[3] = dup2(xv.w);
            ull wp[4];
#pragma unroll
            for (int p = 0; p < 4; ++p)
                wp[p] = *(const ull*)&Ws[kk][ty * 8 + 2 * p];
#pragma unroll
            for (int p = 0; p < 4; ++p)
#pragma unroll
                for (int q = 0; q < 4; ++q)
                    acc2[p][q] = ffma2(wp[p], dx[q], acc2[p][q]);
        }
        __syncthreads();
    }
#pragma unroll
    for (int p = 0; p < 4; ++p) {
        int oc0 = ty * 8 + 2 * p, oc1 = oc0 + 1;
        float2 u0 = unpk2(acc2[p][0]), u1 = unpk2(acc2[p][1]);
        float2 u2 = unpk2(acc2[p][2]), u3 = unpk2(acc2[p][3]);
        size_t i0 = (size_t)(b * CC + oc0) * TF + p0 + tx * 4;
        size_t i1 = (size_t)(b * CC + oc1) * TF + p0 + tx * 4;
        float bv0 = bias[oc0], bv1 = bias[oc1];
        float4 s0 = *(const float4*)&skip[i0];
        float4 s1 = *(const float4*)&skip[i1];
        float4 o0, o1;
        o0.x = u0.x + bv0 + s0.x; o0.y = u1.x + bv0 + s0.y;
        o0.z = u2.x + bv0 + s0.z; o0.w = u3.x + bv0 + s0.w;
        o1.x = u0.y + bv1 + s1.x; o1.y = u1.y + bv1 + s1.y;
        o1.z = u2.y + bv1 + s1.z; o1.w = u3.y + bv1 + s1.w;
        *(float4*)&out[i0] = o0;
        *(float4*)&out[i1] = o1;
    }
}

// ---------------- weight transpose for convt ----------------
__global__ __launch_bounds__(256) void k_wtT(const float* __restrict__ src,
                                             float* __restrict__ dst)
{
    int i = blockIdx.x * 256 + threadIdx.x;
    if (i < 3 * CC * CC) {
        int oc = i & 127, ic = (i >> 7) & 127, tap = i >> 14;
        dst[i] = src[(oc * CC + ic) * 3 + tap];
    }
}

// ---------------- transposed conv over freq (k=3,s=2) + ReLU, f32x2 ----------
__global__ __launch_bounds__(128) void k_convt(float* __restrict__ out,
                                               const float* __restrict__ in,
                                               const float* __restrict__ wT,
                                               const float* __restrict__ bias,
                                               int Fin, int TF)
{
    __shared__ __align__(16) float Xs[128][36];
    __shared__ __align__(16) float Ws[3][16][128];
    int tid = threadIdx.x;
    int tx = tid & 7, ty = tid >> 3;
    int b = blockIdx.y;
    int p0 = blockIdx.x * 32;

#pragma unroll
    for (int i = 0; i < 8; ++i) {
        int e4 = tid + i * 128;
        int ch = e4 >> 3, pq = (e4 & 7) << 2;
        *(float4*)&Xs[ch][pq] = *(const float4*)&in[(size_t)(b * CC + ch) * TF + p0 + pq];
    }
    int p_ = tx * 4;
    bool sh[4];
#pragma unroll
    for (int jj = 0; jj < 4; ++jj) sh[jj] = (((p_ + jj) & (Fin - 1)) != Fin - 1);

    ull ae2[4][4], ao2[4][4];
#pragma unroll
    for (int p = 0; p < 4; ++p)
#pragma unroll
        for (int q = 0; q < 4; ++q) { ae2[p][q] = 0ull; ao2[p][q] = 0ull; }

    for (int kb = 0; kb < CC; kb += 16) {
        __syncthreads();
#pragma unroll
        for (int i = 0; i < 12; ++i) {
            int idx = tid + i * 128;
            int tap = idx / 512, rem = idx & 511;
            int kkk = rem >> 5, oc4 = (rem & 31) << 2;
            *(float4*)&Ws[tap][kkk][oc4] =
                *(const float4*)&wT[(tap * CC + kb + kkk) * CC + oc4];
        }
        __syncthreads();
#pragma unroll
        for (int kk = 0; kk < 16; ++kk) {
            const float* xrow = &Xs[kb + kk][0];
            float4 xv = *(const float4*)&xrow[p_];
            float xnext = xrow[p_ + 4];
            ull dx[4], dxs[4];
            dx[0] = dup2(xv.x); dx[1] = dup2(xv.y);
            dx[2] = dup2(xv.z); dx[3] = dup2(xv.w);
            dxs[0] = dup2(sh[0] ? xv.y : 0.f);
            dxs[1] = dup2(sh[1] ? xv.z : 0.f);
            dxs[2] = dup2(sh[2] ? xv.w : 0.f);
            dxs[3] = dup2(sh[3] ? xnext : 0.f);
            ull w0p[4], w1p[4], w2p[4];
#pragma unroll
            for (int p = 0; p < 4; ++p) {
                w0p[p] = *(const ull*)&Ws[0][kk][ty * 8 + 2 * p];
                w1p[p] = *(const ull*)&Ws[1][kk][ty * 8 + 2 * p];
                w2p[p] = *(const ull*)&Ws[2][kk][ty * 8 + 2 * p];
            }
#pragma unroll
            for (int p = 0; p < 4; ++p)
#pragma unroll
                for (int q = 0; q < 4; ++q) {
                    ae2[p][q] = ffma2(w1p[p], dx[q], ae2[p][q]);
                    ao2[p][q] = ffma2(w0p[p], dx[q], ao2[p][q]);
                    ao2[p][q] = ffma2(w2p[p], dxs[q], ao2[p][q]);
                }
        }
    }
    int TF2 = TF * 2;
#pragma unroll
    for (int p = 0; p < 4; ++p) {
        int oc0 = ty * 8 + 2 * p, oc1 = oc0 + 1;
        float bv0 = bias[oc0], bv1 = bias[oc1];
#pragma unroll
        for (int q = 0; q < 4; ++q) {
            int pp = p0 + p_ + q;
            float2 e = unpk2(ae2[p][q]);
            float2 o = unpk2(ao2[p][q]);
            float2 r0, r1;
            r0.x = fmaxf(e.x + bv0, 0.f); r0.y = fmaxf(o.x + bv0, 0.f);
            r1.x = fmaxf(e.y + bv1, 0.f); r1.y = fmaxf(o.y + bv1, 0.f);
            *(float2*)&out[(size_t)(b * CC + oc0) * TF2 + 2 * pp] = r0;
            *(float2*)&out[(size_t)(b * CC + oc1) * TF2 + 2 * pp] = r1;
        }
    }
}

// ---------------- final: pre = w0p@e0 + b0p + e1x ; m = sigmoid(conv3(pre)) ----
__global__ __launch_bounds__(256) void k_final(const float* __restrict__ e0,
                                               const float* __restrict__ W,
                                               const float* __restrict__ bias,
                                               const float* __restrict__ w0o,
                                               const float* __restrict__ b0o,
                                               float* __restrict__ outm)
{
    __shared__ __align__(16) float Xs[128][64];
    __shared__ __align__(16) float Ws[16][128];
    __shared__ float wo[128][3];
    const int TF = TT * 64;
    int tid = threadIdx.x;
    int tx = tid & 15, ty = tid >> 4;
    int b = blockIdx.y, t = blockIdx.x;
    int p0 = t * 64;

#pragma unroll
    for (int i = 0; i < 8; ++i) {
        int e4 = tid + i * 256;
        int ch = e4 >> 4, pq = (e4 & 15) << 2;
        *(float4*)&Xs[ch][pq] = *(const float4*)&e0[(size_t)(b * CC + ch) * TF + p0 + pq];
    }
    for (int i = tid; i < 384; i += 256) wo[i / 3][i % 3] = w0o[i];

    ull acc2[4][4];
#pragma unroll
    for (int p = 0; p < 4; ++p)
#pragma unroll
        for (int q = 0; q < 4; ++q) acc2[p][q] = 0ull;

    for (int kb = 0; kb < CC; kb += 16) {
#pragma unroll
        for (int i = 0; i < 2; ++i) {
            int e4 = tid * 2 + i;
            int oc = e4 >> 2, k4 = (e4 & 3) << 2;
            float4 v = *(const float4*)&W[oc * CC + kb + k4];
            Ws[k4 + 0][oc] = v.x; Ws[k4 + 1][oc] = v.y;
            Ws[k4 + 2][oc] = v.z; Ws[k4 + 3][oc] = v.w;
        }
        __syncthreads();
#pragma unroll
        for (int kk = 0; kk < 16; ++kk) {
            float4 xv = *(const float4*)&Xs[kb + kk][tx * 4];
            ull dx[4];
            dx[0] = dup2(xv.x); dx[1] = dup2(xv.y);
            dx[2] = dup2(xv.z); dx[3] = dup2(xv.w);
            ull wp[4];
#pragma unroll
            for (int p = 0; p < 4; ++p)
                wp[p] = *(const ull*)&Ws[kk][ty * 8 + 2 * p];
#pragma unroll
            for (int p = 0; p < 4; ++p)
#pragma unroll
                for (int q = 0; q < 4; ++q)
                    acc2[p][q] = ffma2(wp[p], dx[q], acc2[p][q]);
        }
        __syncthreads();
    }
#pragma unroll
    for (int p = 0; p < 4; ++p) {
        int oc0 = ty * 8 + 2 * p, oc1 = oc0 + 1;
        float bv0 = bias[oc0], bv1 = bias[oc1];
        float2 u0 = unpk2(acc2[p][0]), u1 = unpk2(acc2[p][1]);
        float2 u2 = unpk2(acc2[p][2]), u3 = unpk2(acc2[p][3]);
        int pq = tx * 4;
        Xs[oc0][pq + 0] = u0.x + bv0 + g_e1x[(size_t)(b * CC + oc0) * TF + p0 + pq + 0];
        Xs[oc0][pq + 1] = u1.x + bv0 + g_e1x[(size_t)(b * CC + oc0) * TF + p0 + pq + 1];
        Xs[oc0][pq + 2] = u2.x + bv0 + g_e1x[(size_t)(b * CC + oc0) * TF + p0 + pq + 2];
        Xs[oc0][pq + 3] = u3.x + bv0 + g_e1x[(size_t)(b * CC + oc0) * TF + p0 + pq + 3];
        Xs[oc1][pq + 0] = u0.y + bv1 + g_e1x[(size_t)(b * CC + oc1) * TF + p0 + pq + 0];
        Xs[oc1][pq + 1] = u1.y + bv1 + g_e1x[(size_t)(b * CC + oc1) * TF + p0 + pq + 1];
        Xs[oc1][pq + 2] = u2.y + bv1 + g_e1x[(size_t)(b * CC + oc1) * TF + p0 + pq + 2];
        Xs[oc1][pq + 3] = u3.y + bv1 + g_e1x[(size_t)(b * CC + oc1) * TF + p0 + pq + 3];
    }
    __syncthreads();
    int f = tid >> 2, q = tid & 3;
    float s = 0.f;
#pragma unroll 4
    for (int i = 0; i < 32; ++i) {
        int ch = q * 32 + i;
        float x0 = Xs[ch][f];
        float xm = (f > 0) ? Xs[ch][f - 1] : 0.f;
        float xp = (f < 63) ? Xs[ch][f + 1] : 0.f;
        s = fmaf(wo[ch][0], xm, s);
        s = fmaf(wo[ch][1], x0, s);
        s = fmaf(wo[ch][2], xp, s);
    }
    s += __shfl_down_sync(0xffffffffu, s, 1);
    s += __shfl_down_sync(0xffffffffu, s, 2);
    if (q == 0) outm[((size_t)b * TT + t) * 64 + f] = 1.f / (1.f + __expf(-(s + b0o[0])));
}

// ---------------------------------- launch ----------------------------------
extern "C" void kernel_launch(void* const* d_in, const int* in_sizes, int n_in,
                              void* d_out, int out_size)
{
    const float* emb   = (const float*)d_in[0];
    const float* e3    = (const float*)d_in[1];
    const float* e2    = (const float*)d_in[2];
    const float* e1    = (const float*)d_in[3];
    const float* e0    = (const float*)d_in[4];
    const float* h_erb = (const float*)d_in[5];
    const float* Wih   = (const float*)d_in[6];
    const float* Whh   = (const float*)d_in[7];
    const float* bih   = (const float*)d_in[8];
    const float* bhh   = (const float*)d_in[9];
    const float* w3p   = (const float*)d_in[10];
    const float* b3p   = (const float*)d_in[11];
    const float* w2p   = (const float*)d_in[12];
    const float* b2p   = (const float*)d_in[13];
    const float* w1p   = (const float*)d_in[14];
    const float* b1p   = (const float*)d_in[15];
    const float* w0p   = (const float*)d_in[16];
    const float* b0p   = (const float*)d_in[17];
    const float* wt3   = (const float*)d_in[18];
    const float* bt3   = (const float*)d_in[19];
    const float* wt2   = (const float*)d_in[20];
    const float* bt2   = (const float*)d_in[21];
    const float* wt1   = (const float*)d_in[22];
    const float* bt1   = (const float*)d_in[23];
    const float* w0o   = (const float*)d_in[24];
    const float* b0o   = (const float*)d_in[25];
    float* out = (float*)d_out;

    float* gx3;  cudaGetSymbolAddress((void**)&gx3,  g_x3);
    float* ge3x; cudaGetSymbolAddress((void**)&ge3x, g_e3x);
    float* gx2;  cudaGetSymbolAddress((void**)&gx2,  g_x2);
    float* ge2x; cudaGetSymbolAddress((void**)&ge2x, g_e2x);
    float* gx1;  cudaGetSymbolAddress((void**)&gx1,  g_x1);
    float* ge1x; cudaGetSymbolAddress((void**)&ge1x, g_e1x);
    float* gemb2;cudaGetSymbolAddress((void**)&gemb2,g_emb2);
    float* gw3;  cudaGetSymbolAddress((void**)&gw3,  g_wtT3);
    float* gw2;  cudaGetSymbolAddress((void**)&gw2,  g_wtT2);
    float* gw1;  cudaGetSymbolAddress((void**)&gw1,  g_wtT1);
    void *pAh, *pAl, *pWh, *pWl;
    cudaGetSymbolAddress(&pAh, g_Ah);
    cudaGetSymbolAddress(&pAl, g_Al);
    cudaGetSymbolAddress(&pWh, g_Wh);
    cudaGetSymbolAddress(&pWl, g_Wl);

    cudaFuncSetAttribute(k_gru, cudaFuncAttributeMaxDynamicSharedMemorySize, GRU_SMEM);

    // launch order chosen so ncu (-s 5 -c 1) profiles k_gru (index 5)
    k_split<<<4096, 256>>>((const float4*)emb,
                           (ushort4*)pAh, (ushort4*)pAl, 1048576);  // 0
    k_split<<<3072, 256>>>((const float4*)Wih,
                           (ushort4*)pWh, (ushort4*)pWl, 786432);   // 1
    k_xg_mma<<<dim3(48, 32), 256>>>(bih);                           // 2
    k_wtT<<<192, 256>>>(wt3, gw3);                                  // 3
    k_reset<<<1, 32>>>();                                           // 4
    k_gru<<<GBLK, 256, GRU_SMEM>>>(h_erb, Whh, bhh, out + BB * TT * 64); // 5
    k_wtT<<<192, 256>>>(wt2, gw2);                                  // 6
    k_wtT<<<192, 256>>>(wt1, gw1);                                  // 7

    k_pconv<<<dim3(64, 8),  256>>>(gx3, e3, w3p, b3p, gemb2, TT * 8);
    k_convt<<<dim3(128, 8), 128>>>(ge3x, gx3, gw3, bt3, 8, TT * 8);

    k_pconv<<<dim3(128, 8), 256>>>(gx2, e2, w2p, b2p, ge3x, TT * 16);
    k_convt<<<dim3(256, 8), 128>>>(ge2x, gx2, gw2, bt2, 16, TT * 16);

    k_pconv<<<dim3(256, 8), 256>>>(gx1, e1, w1p, b1p, ge2x, TT * 32);
    k_convt<<<dim3(512, 8), 128>>>(ge1x, gx1, gw1, bt1, 32, TT * 32);

    k_final<<<dim3(512, 8), 256>>>(e0, w0p, b0p, w0o, b0o, out);
}

// round 12
// speedup vs baseline: 1.1767x; 1.0136x over previous
#include <cuda_runtime.h>
#include <cuda_bf16.h>

#define BB 8
#define TT 512
#define CC 128
#define HH 1024
#define GBLK 148
#define GW 7

typedef unsigned long long ull;
typedef unsigned short ushort_t;

// ---------------- f32x2 helpers (decoder kernels) ----------------
__device__ __forceinline__ ull dup2(float x)
{
    ull r;
    asm("mov.b64 %0, {%1, %1};" : "=l"(r) : "f"(x));
    return r;
}
__device__ __forceinline__ ull ffma2(ull a, ull b, ull c)
{
    ull d;
    asm("fma.rn.f32x2 %0, %1, %2, %3;" : "=l"(d) : "l"(a), "l"(b), "l"(c));
    return d;
}
__device__ __forceinline__ float2 unpk2(ull v)
{
    float2 f;
    asm("mov.b64 {%0, %1}, %2;" : "=f"(f.x), "=f"(f.y) : "l"(v));
    return f;
}

// ---------------- static scratch ----------------
__device__ float g_xg[BB * TT * 3 * HH];
__device__ float g_h[2][BB * HH];
__device__ float g_emb2[BB * CC * TT * 8];
__device__ float g_x3[BB * CC * TT * 8];
__device__ float g_e3x[BB * CC * TT * 16];
__device__ float g_x2[BB * CC * TT * 16];
__device__ float g_e2x[BB * CC * TT * 32];
__device__ float g_x1[BB * CC * TT * 32];
__device__ float g_e1x[BB * CC * TT * 64];
__device__ float g_p0[BB * CC * TT * 64];
__device__ float g_wtT3[3 * CC * CC];
__device__ float g_wtT2[3 * CC * CC];
__device__ float g_wtT1[3 * CC * CC];
__device__ unsigned short g_Ah[BB * TT * HH];
__device__ unsigned short g_Al[BB * TT * HH];
__device__ unsigned short g_Wh[3 * HH * HH];
__device__ unsigned short g_Wl[3 * HH * HH];
__device__ unsigned g_bar_count;
__device__ unsigned g_bar_gen;

// ---------------- barrier state reset (per launch) ----------------
__global__ void k_reset()
{
    if (threadIdx.x == 0) { g_bar_count = 0; g_bar_gen = 0; }
}

// ---------------- acquire/release grid barrier ----------------
__device__ __forceinline__ void grid_barrier(unsigned my_gen)
{
    __syncthreads();
    if (threadIdx.x == 0) {
        unsigned arr;
        asm volatile("atom.add.release.gpu.u32 %0, [%1], 1;"
                     : "=r"(arr) : "l"(&g_bar_count) : "memory");
        if (arr == GBLK - 1) {
            g_bar_count = 0;
            asm volatile("st.release.gpu.u32 [%0], %1;"
                         :: "l"(&g_bar_gen), "r"(my_gen) : "memory");
        } else {
            unsigned cur;
            do {
                asm volatile("ld.acquire.gpu.u32 %0, [%1];"
                             : "=r"(cur) : "l"(&g_bar_gen) : "memory");
            } while ((int)(cur - my_gen) < 0);
        }
    }
    __syncthreads();
}

// ---------------- splitting helper ----------------
__device__ __forceinline__ void split1(float v, unsigned short& h, unsigned short& l)
{
    __nv_bfloat16 bh = __float2bfloat16(v);
    float r = v - __bfloat162float(bh);
    __nv_bfloat16 bl = __float2bfloat16(r);
    h = *(unsigned short*)&bh;
    l = *(unsigned short*)&bl;
}

// ---------------- bf16 hi/lo split: fp32 tensor -> (hi, lo) ----------------
__global__ __launch_bounds__(256) void k_split(const float4* __restrict__ src,
                                               ushort4* __restrict__ hi,
                                               ushort4* __restrict__ lo,
                                               int n4)
{
    int i = blockIdx.x * 256 + threadIdx.x;
    if (i >= n4) return;
    float4 v = src[i];
    float f[4] = { v.x, v.y, v.z, v.w };
    unsigned short h[4], l[4];
#pragma unroll
    for (int q = 0; q < 4; ++q) split1(f[q], h[q], l[q]);
    hi[i] = make_ushort4(h[0], h[1], h[2], h[3]);
    lo[i] = make_ushort4(l[0], l[1], l[2], l[3]);
}

// ---------------- mma helpers (sm_80-baseline PTX) ----------------
__device__ __forceinline__ unsigned smem_u32(const void* p)
{
    unsigned a;
    asm("{ .reg .u64 t; cvta.to.shared.u64 t, %1; cvt.u32.u64 %0, t; }"
        : "=r"(a) : "l"(p));
    return a;
}
__device__ __forceinline__ void ldsm4(unsigned* r, unsigned addr)
{
    asm volatile("ldmatrix.sync.aligned.m8n8.x4.shared.b16 {%0,%1,%2,%3}, [%4];"
        : "=r"(r[0]), "=r"(r[1]), "=r"(r[2]), "=r"(r[3]) : "r"(addr));
}
__device__ __forceinline__ void ldsm2(unsigned* r, unsigned addr)
{
    asm volatile("ldmatrix.sync.aligned.m8n8.x2.shared.b16 {%0,%1}, [%2];"
        : "=r"(r[0]), "=r"(r[1]) : "r"(addr));
}
__device__ __forceinline__ void mma16816(float* d, const unsigned* a, const unsigned* b)
{
    asm volatile("mma.sync.aligned.m16n8k16.row.col.f32.bf16.bf16.f32 "
        "{%0,%1,%2,%3}, {%4,%5,%6,%7}, {%8,%9}, {%0,%1,%2,%3};"
        : "+f"(d[0]), "+f"(d[1]), "+f"(d[2]), "+f"(d[3])
        : "r"(a[0]), "r"(a[1]), "r"(a[2]), "r"(a[3]), "r"(b[0]), "r"(b[1]));
}

// ---------------- xg = emb @ Wih^T + bih : mma.sync split-bf16 ----------------
__global__ __launch_bounds__(256) void k_xg_mma(const float* __restrict__ bias)
{
    __shared__ __align__(16) unsigned short sAh[128][40];
    __shared__ __align__(16) unsigned short sAl[128][40];
    __shared__ __align__(16) unsigned short sWh[64][40];
    __shared__ __align__(16) unsigned short sWl[64][40];
    int tid = threadIdx.x, lane = tid & 31, wid = tid >> 5;
    int wm = wid >> 1, wn = wid & 1;
    int m0 = blockIdx.y * 128, n0 = blockIdx.x * 64;

    float acc[2][4][4];
#pragma unroll
    for (int mi = 0; mi < 2; ++mi)
#pragma unroll
        for (int ni = 0; ni < 4; ++ni)
#pragma unroll
            for (int q = 0; q < 4; ++q) acc[mi][ni][q] = 0.f;

    for (int kc = 0; kc < HH; kc += 32) {
        __syncthreads();
#pragma unroll
        for (int i = 0; i < 6; ++i) {
            int idx = tid + i * 256;
            const uint4* src;
            unsigned short* dst;
            if (idx < 512) {
                int row = idx >> 2, c8 = (idx & 3) * 8;
                src = (const uint4*)&g_Ah[(size_t)(m0 + row) * HH + kc + c8];
                dst = &sAh[row][c8];
            } else if (idx < 1024) {
                int e = idx - 512;
                int row = e >> 2, c8 = (e & 3) * 8;
                src = (const uint4*)&g_Al[(size_t)(m0 + row) * HH + kc + c8];
                dst = &sAl[row][c8];
            } else if (idx < 1280) {
                int e = idx - 1024;
                int row = e >> 2, c8 = (e & 3) * 8;
                src = (const uint4*)&g_Wh[(size_t)(n0 + row) * HH + kc + c8];
                dst = &sWh[row][c8];
            } else {
                int e = idx - 1280;
                int row = e >> 2, c8 = (e & 3) * 8;
                src = (const uint4*)&g_Wl[(size_t)(n0 + row) * HH + kc + c8];
                dst = &sWl[row][c8];
            }
            *(uint4*)dst = *src;
        }
        __syncthreads();

#pragma unroll
        for (int ks = 0; ks < 2; ++ks) {
            int k0 = ks * 16;
            unsigned ah[2][4], al[2][4];
#pragma unroll
            for (int mi = 0; mi < 2; ++mi) {
                int m = wm * 32 + mi * 16 + (lane & 15);
                int kk = k0 + (lane >> 4) * 8;
                ldsm4(ah[mi], smem_u32(&sAh[m][kk]));
                ldsm4(al[mi], smem_u32(&sAl[m][kk]));
            }
            unsigned bh[4][2], bl[4][2];
#pragma unroll
            for (int ni = 0; ni < 4; ++ni) {
                int r = lane & 15;
                int n = wn * 32 + ni * 8 + (r & 7);
                int kk = k0 + (r >> 3) * 8;
                ldsm2(bh[ni], smem_u32(&sWh[n][kk]));
                ldsm2(bl[ni], smem_u32(&sWl[n][kk]));
            }
#pragma unroll
            for (int mi = 0; mi < 2; ++mi)
#pragma unroll
                for (int ni = 0; ni < 4; ++ni) {
                    mma16816(acc[mi][ni], ah[mi], bh[ni]);
                    mma16816(acc[mi][ni], ah[mi], bl[ni]);
                    mma16816(acc[mi][ni], al[mi], bh[ni]);
                }
        }
    }
    int gr = lane >> 2, gc = (lane & 3) * 2;
#pragma unroll
    for (int mi = 0; mi < 2; ++mi)
#pragma unroll
        for (int ni = 0; ni < 4; ++ni) {
            int m = m0 + wm * 32 + mi * 16 + gr;
            int n = n0 + wn * 32 + ni * 8 + gc;
            float b0 = bias[n], b1 = bias[n + 1];
            float2 v0 = { acc[mi][ni][0] + b0, acc[mi][ni][1] + b1 };
            float2 v1 = { acc[mi][ni][2] + b0, acc[mi][ni][3] + b1 };
            *(float2*)&g_xg[(size_t)m * (3 * HH) + n] = v0;
            *(float2*)&g_xg[(size_t)(m + 8) * (3 * HH) + n] = v1;
        }
}

// ---------------- persistent GRU via mma.sync split-bf16 ----------------
#define GRU_STRIDE 1032
#define OFF_WH 0
#define OFF_WL 66048
#define OFF_HH 132096
#define OFF_HL 148608
#define OFF_RED 165120
#define OFF_G 173312
#define GRU_SMEM 174336

__global__ __launch_bounds__(256) void k_gru(const float* __restrict__ h0,
                                             const float* __restrict__ Whh,
                                             const float* __restrict__ bhh,
                                             float* __restrict__ outHT)
{
    extern __shared__ char gsm[];
    ushort_t (*sWh)[GRU_STRIDE] = (ushort_t(*)[GRU_STRIDE])(gsm + OFF_WH);
    ushort_t (*sWl)[GRU_STRIDE] = (ushort_t(*)[GRU_STRIDE])(gsm + OFF_WL);
    ushort_t (*sHh)[GRU_STRIDE] = (ushort_t(*)[GRU_STRIDE])(gsm + OFF_HH);
    ushort_t (*sHl)[GRU_STRIDE] = (ushort_t(*)[GRU_STRIDE])(gsm + OFF_HL);
    float (*sRed)[32][8] = (float(*)[32][8])(gsm + OFF_RED);
    float (*sG)[8] = (float(*)[8])(gsm + OFF_G);

    int tid = threadIdx.x, lane = tid & 31, wid = tid >> 5;

    int eu = tid >> 3, eb = tid & 7;
    int ej = blockIdx.x * GW + eu;
    bool epv = (tid < 56) && (ej < HH);
    float br_ = 0.f, bz_ = 0.f, bn_ = 0.f;
    int ec = ej & 127, ef = ej >> 7;
    if (epv) { br_ = bhh[ej]; bz_ = bhh[ej + HH]; bn_ = bhh[ej + 2 * HH]; }

    for (int idx = tid; idx < 32 * HH; idx += 256) {
        int row = idx >> 10, k = idx & 1023;
        float v = 0.f;
        if (row < 21) {
            int unit = row / 3, gate = row - unit * 3;
            int j = blockIdx.x * GW + unit;
            if (j < HH) v = Whh[(size_t)(j + gate * HH) * HH + k];
        }
        unsigned short h, l;
        split1(v, h, l);
        sWh[row][k] = h;
        sWl[row][k] = l;
    }

    unsigned my_gen = 0;
    {
        int i = blockIdx.x * 256 + tid;
        if (i < BB * HH) g_h[0][i] = h0[i];
    }
    ++my_gen;
    grid_barrier(my_gen);

    int kbase = wid * 128;

    for (int t = 0; t < TT; ++t) {
        float xr = 0.f, xz = 0.f, xn = 0.f, hprev = 0.f;
        if (epv) {
            const float* xgp = g_xg + ((size_t)eb * TT + t) * (3 * HH);
            xr = xgp[ej]; xz = xgp[ej + HH]; xn = xgp[ej + 2 * HH];
            hprev = g_h[t & 1][eb * HH + ej];
        }
        const float4* hp = (const float4*)&g_h[t & 1][0];
#pragma unroll
        for (int i = 0; i < 8; ++i) {
            int idx4 = tid + i * 256;
            float4 v = hp[idx4];
            int b = idx4 >> 8, k4 = (idx4 & 255) * 4;
            unsigned short h0_, l0_, h1_, l1_, h2_, l2_, h3_, l3_;
            split1(v.x, h0_, l0_);
            split1(v.y, h1_, l1_);
            split1(v.z, h2_, l2_);
            split1(v.w, h3_, l3_);
            *(ushort4*)&sHh[b][k4] = make_ushort4(h0_, h1_, h2_, h3_);
            *(ushort4*)&sHl[b][k4] = make_ushort4(l0_, l1_, l2_, l3_);
        }
        __syncthreads();

        float a0[2][4], a1[2][4], a2[2][4];
#pragma unroll
        for (int mi = 0; mi < 2; ++mi)
#pragma unroll
            for (int q = 0; q < 4; ++q) { a0[mi][q] = 0.f; a1[mi][q] = 0.f; a2[mi][q] = 0.f; }

#pragma unroll
        for (int ks = 0; ks < 8; ++ks) {
            int kk = kbase + ks * 16;
            unsigned bh[2], bl[2];
            int r = lane & 15;
            ldsm2(bh, smem_u32(&sHh[r & 7][kk + (r >> 3) * 8]));
            ldsm2(bl, smem_u32(&sHl[r & 7][kk + (r >> 3) * 8]));
            unsigned ah[2][4], al[2][4];
#pragma unroll
            for (int mi = 0; mi < 2; ++mi) {
                int m = mi * 16 + (lane & 15);
                int kko = kk + (lane >> 4) * 8;
                ldsm4(ah[mi], smem_u32(&sWh[m][kko]));
                ldsm4(al[mi], smem_u32(&sWl[m][kko]));
            }
#pragma unroll
            for (int mi = 0; mi < 2; ++mi) {
                mma16816(a0[mi], ah[mi], bh);
                mma16816(a1[mi], ah[mi], bl);
                mma16816(a2[mi], al[mi], bh);
            }
        }
        int gr = lane >> 2, gc = (lane & 3) * 2;
#pragma unroll
        for (int mi = 0; mi < 2; ++mi) {
            sRed[wid][mi * 16 + gr][gc]         = a0[mi][0] + a1[mi][0] + a2[mi][0];
            sRed[wid][mi * 16 + gr][gc + 1]     = a0[mi][1] + a1[mi][1] + a2[mi][1];
            sRed[wid][mi * 16 + gr + 8][gc]     = a0[mi][2] + a1[mi][2] + a2[mi][2];
            sRed[wid][mi * 16 + gr + 8][gc + 1] = a0[mi][3] + a1[mi][3] + a2[mi][3];
        }
        __syncthreads();
        {
            int row = tid >> 3, col = tid & 7;
            float s = 0.f;
#pragma unroll
            for (int w = 0; w < 8; ++w) s += sRed[w][row][col];
            sG[row][col] = s;
        }
        __syncthreads();
        if (epv) {
            float sr = sG[eu * 3 + 0][eb];
            float sz = sG[eu * 3 + 1][eb];
            float sn = sG[eu * 3 + 2][eb];
            float r = 1.f / (1.f + __expf(-(xr + sr + br_)));
            float z = 1.f / (1.f + __expf(-(xz + sz + bz_)));
            float n = tanhf(xn + r * (sn + bn_));
            float hnew = (1.f - z) * n + z * hprev;
            g_h[(t + 1) & 1][eb * HH + ej] = hnew;
            g_emb2[((size_t)(eb * CC + ec) * TT + t) * 8 + ef] = hnew;
            if (t == TT - 1) outHT[eb * HH + ej] = hnew;
        }
        ++my_gen;
        grid_barrier(my_gen);
    }
}

// ---------------- pconvP: P = W @ x + bias (no skip), f32x2 ----------------
__global__ __launch_bounds__(256) void k_pconvP(float* __restrict__ out,
                                                const float* __restrict__ in,
                                                const float* __restrict__ W,
                                                const float* __restrict__ bias,
                                                int TF)
{
    __shared__ __align__(16) float Xs[128][64];
    __shared__ __align__(16) float Ws[16][128];
    int tid = threadIdx.x;
    int tx = tid & 15, ty = tid >> 4;
    int b = blockIdx.y;
    int p0 = blockIdx.x * 64;

#pragma unroll
    for (int i = 0; i < 8; ++i) {
        int e4 = tid + i * 256;
        int ch = e4 >> 4, pq = (e4 & 15) << 2;
        *(float4*)&Xs[ch][pq] = *(const float4*)&in[(size_t)(b * CC + ch) * TF + p0 + pq];
    }
    ull acc2[4][4];
#pragma unroll
    for (int p = 0; p < 4; ++p)
#pragma unroll
        for (int q = 0; q < 4; ++q) acc2[p][q] = 0ull;

    for (int kb = 0; kb < CC; kb += 16) {
#pragma unroll
        for (int i = 0; i < 2; ++i) {
            int e4 = tid * 2 + i;
            int oc = e4 >> 2, k4 = (e4 & 3) << 2;
            float4 v = *(const float4*)&W[oc * CC + kb + k4];
            Ws[k4 + 0][oc] = v.x; Ws[k4 + 1][oc] = v.y;
            Ws[k4 + 2][oc] = v.z; Ws[k4 + 3][oc] = v.w;
        }
        __syncthreads();
#pragma unroll
        for (int kk = 0; kk < 16; ++kk) {
            float4 xv = *(const float4*)&Xs[kb + kk][tx * 4];
            ull dx[4];
            dx[0] = dup2(xv.x); dx[1] = dup2(xv.y);
            dx[2] = dup2(xv.z); dx[3] = dup2(xv.w);
            ull wp[4];
#pragma unroll
            for (int p = 0; p < 4; ++p)
                wp[p] = *(const ull*)&Ws[kk][ty * 8 + 2 * p];
#pragma unroll
            for (int p = 0; p < 4; ++p)
#pragma unroll
                for (int q = 0; q < 4; ++q)
                    acc2[p][q] = ffma2(wp[p], dx[q], acc2[p][q]);
        }
        __syncthreads();
    }
#pragma unroll
    for (int p = 0; p < 4; ++p) {
        int oc0 = ty * 8 + 2 * p, oc1 = oc0 + 1;
        float2 u0 = unpk2(acc2[p][0]), u1 = unpk2(acc2[p][1]);
        float2 u2 = unpk2(acc2[p][2]), u3 = unpk2(acc2[p][3]);
        size_t i0 = (size_t)(b * CC + oc0) * TF + p0 + tx * 4;
        size_t i1 = (size_t)(b * CC + oc1) * TF + p0 + tx * 4;
        float bv0 = bias[oc0], bv1 = bias[oc1];
        float4 o0, o1;
        o0.x = u0.x + bv0; o0.y = u1.x + bv0;
        o0.z = u2.x + bv0; o0.w = u3.x + bv0;
        o1.x = u0.y + bv1; o1.y = u1.y + bv1;
        o1.z = u2.y + bv1; o1.w = u3.y + bv1;
        *(float4*)&out[i0] = o0;
        *(float4*)&out[i1] = o1;
    }
}

// ---------------- weight transpose for convt ----------------
__global__ __launch_bounds__(256) void k_wtT(const float* __restrict__ src,
                                             float* __restrict__ dst)
{
    int i = blockIdx.x * 256 + threadIdx.x;
    if (i < 3 * CC * CC) {
        int oc = i & 127, ic = (i >> 7) & 127, tap = i >> 14;
        dst[i] = src[(oc * CC + ic) * 3 + tap];
    }
}

// ---------------- convt (k=3,s=2) + ReLU, fused skip-add input, f32x2 ---------
__global__ __launch_bounds__(128) void k_convt(float* __restrict__ out,
                                               const float* __restrict__ in,
                                               const float* __restrict__ skip,
                                               const float* __restrict__ wT,
                                               const float* __restrict__ bias,
                                               int Fin, int TF)
{
    __shared__ __align__(16) float Xs[128][36];
    __shared__ __align__(16) float Ws[3][16][128];
    int tid = threadIdx.x;
    int tx = tid & 7, ty = tid >> 3;
    int b = blockIdx.y;
    int p0 = blockIdx.x * 32;

#pragma unroll
    for (int i = 0; i < 8; ++i) {
        int e4 = tid + i * 128;
        int ch = e4 >> 3, pq = (e4 & 7) << 2;
        size_t gi = (size_t)(b * CC + ch) * TF + p0 + pq;
        float4 a = *(const float4*)&in[gi];
        float4 s = *(const float4*)&skip[gi];
        a.x += s.x; a.y += s.y; a.z += s.z; a.w += s.w;
        *(float4*)&Xs[ch][pq] = a;
    }
    int p_ = tx * 4;
    bool sh[4];
#pragma unroll
    for (int jj = 0; jj < 4; ++jj) sh[jj] = (((p_ + jj) & (Fin - 1)) != Fin - 1);

    ull ae2[4][4], ao2[4][4];
#pragma unroll
    for (int p = 0; p < 4; ++p)
#pragma unroll
        for (int q = 0; q < 4; ++q) { ae2[p][q] = 0ull; ao2[p][q] = 0ull; }

    for (int kb = 0; kb < CC; kb += 16) {
        __syncthreads();
#pragma unroll
        for (int i = 0; i < 12; ++i) {
            int idx = tid + i * 128;
            int tap = idx / 512, rem = idx & 511;
            int kkk = rem >> 5, oc4 = (rem & 31) << 2;
            *(float4*)&Ws[tap][kkk][oc4] =
                *(const float4*)&wT[(tap * CC + kb + kkk) * CC + oc4];
        }
        __syncthreads();
#pragma unroll
        for (int kk = 0; kk < 16; ++kk) {
            const float* xrow = &Xs[kb + kk][0];
            float4 xv = *(const float4*)&xrow[p_];
            float xnext = xrow[p_ + 4];
            ull dx[4], dxs[4];
            dx[0] = dup2(xv.x); dx[1] = dup2(xv.y);
            dx[2] = dup2(xv.z); dx[3] = dup2(xv.w);
            dxs[0] = dup2(sh[0] ? xv.y : 0.f);
            dxs[1] = dup2(sh[1] ? xv.z : 0.f);
            dxs[2] = dup2(sh[2] ? xv.w : 0.f);
            dxs[3] = dup2(sh[3] ? xnext : 0.f);
            ull w0p[4], w1p[4], w2p[4];
#pragma unroll
            for (int p = 0; p < 4; ++p) {
                w0p[p] = *(const ull*)&Ws[0][kk][ty * 8 + 2 * p];
                w1p[p] = *(const ull*)&Ws[1][kk][ty * 8 + 2 * p];
                w2p[p] = *(const ull*)&Ws[2][kk][ty * 8 + 2 * p];
            }
#pragma unroll
            for (int p = 0; p < 4; ++p)
#pragma unroll
                for (int q = 0; q < 4; ++q) {
                    ae2[p][q] = ffma2(w1p[p], dx[q], ae2[p][q]);
                    ao2[p][q] = ffma2(w0p[p], dx[q], ao2[p][q]);
                    ao2[p][q] = ffma2(w2p[p], dxs[q], ao2[p][q]);
                }
        }
    }
    int TF2 = TF * 2;
#pragma unroll
    for (int p = 0; p < 4; ++p) {
        int oc0 = ty * 8 + 2 * p, oc1 = oc0 + 1;
        float bv0 = bias[oc0], bv1 = bias[oc1];
#pragma unroll
        for (int q = 0; q < 4; ++q) {
            int pp = p0 + p_ + q;
            float2 e = unpk2(ae2[p][q]);
            float2 o = unpk2(ao2[p][q]);
            float2 r0, r1;
            r0.x = fmaxf(e.x + bv0, 0.f); r0.y = fmaxf(o.x + bv0, 0.f);
            r1.x = fmaxf(e.y + bv1, 0.f); r1.y = fmaxf(o.y + bv1, 0.f);
            *(float2*)&out[(size_t)(b * CC + oc0) * TF2 + 2 * pp] = r0;
            *(float2*)&out[(size_t)(b * CC + oc1) * TF2 + 2 * pp] = r1;
        }
    }
}

// ---------------- final lite: pre = P0 + e1x ; m = sigmoid(conv3(pre)) -------
__global__ __launch_bounds__(256) void k_final_lite(const float* __restrict__ P0,
                                                    const float* __restrict__ w0o,
                                                    const float* __restrict__ b0o,
                                                    float* __restrict__ outm)
{
    __shared__ __align__(16) float pre[128][68];
    __shared__ float wo[128][3];
    const int TF = TT * 64;
    int tid = threadIdx.x;
    int b = blockIdx.y, t = blockIdx.x;
    int p0 = t * 64;

    for (int i = tid; i < 384; i += 256) wo[i / 3][i % 3] = w0o[i];
#pragma unroll
    for (int i = 0; i < 8; ++i) {
        int e4 = tid + i * 256;
        int ch = e4 >> 4, pq = (e4 & 15) << 2;
        size_t gi = (size_t)(b * CC + ch) * TF + p0 + pq;
        float4 a = *(const float4*)&P0[gi];
        float4 s = *(const float4*)&g_e1x[gi];
        a.x += s.x; a.y += s.y; a.z += s.z; a.w += s.w;
        *(float4*)&pre[ch][pq] = a;
    }
    __syncthreads();
    int f = tid >> 2, q = tid & 3;
    float s = 0.f;
#pragma unroll 4
    for (int i = 0; i < 32; ++i) {
        int ch = q * 32 + i;
        float x0 = pre[ch][f];
        float xm = (f > 0) ? pre[ch][f - 1] : 0.f;
        float xp = (f < 63) ? pre[ch][f + 1] : 0.f;
        s = fmaf(wo[ch][0], xm, s);
        s = fmaf(wo[ch][1], x0, s);
        s = fmaf(wo[ch][2], xp, s);
    }
    s += __shfl_down_sync(0xffffffffu, s, 1);
    s += __shfl_down_sync(0xffffffffu, s, 2);
    if (q == 0) outm[((size_t)b * TT + t) * 64 + f] = 1.f / (1.f + __expf(-(s + b0o[0])));
}

// ---------------------------------- launch ----------------------------------
extern "C" void kernel_launch(void* const* d_in, const int* in_sizes, int n_in,
                              void* d_out, int out_size)
{
    const float* emb   = (const float*)d_in[0];
    const float* e3    = (const float*)d_in[1];
    const float* e2    = (const float*)d_in[2];
    const float* e1    = (const float*)d_in[3];
    const float* e0    = (const float*)d_in[4];
    const float* h_erb = (const float*)d_in[5];
    const float* Wih   = (const float*)d_in[6];
    const float* Whh   = (const float*)d_in[7];
    const float* bih   = (const float*)d_in[8];
    const float* bhh   = (const float*)d_in[9];
    const float* w3p   = (const float*)d_in[10];
    const float* b3p   = (const float*)d_in[11];
    const float* w2p   = (const float*)d_in[12];
    const float* b2p   = (const float*)d_in[13];
    const float* w1p   = (const float*)d_in[14];
    const float* b1p   = (const float*)d_in[15];
    const float* w0p   = (const float*)d_in[16];
    const float* b0p   = (const float*)d_in[17];
    const float* wt3   = (const float*)d_in[18];
    const float* bt3   = (const float*)d_in[19];
    const float* wt2   = (const float*)d_in[20];
    const float* bt2   = (const float*)d_in[21];
    const float* wt1   = (const float*)d_in[22];
    const float* bt1   = (const float*)d_in[23];
    const float* w0o   = (const float*)d_in[24];
    const float* b0o   = (const float*)d_in[25];
    float* out = (float*)d_out;

    float* gx3;  cudaGetSymbolAddress((void**)&gx3,  g_x3);
    float* ge3x; cudaGetSymbolAddress((void**)&ge3x, g_e3x);
    float* gx2;  cudaGetSymbolAddress((void**)&gx2,  g_x2);
    float* ge2x; cudaGetSymbolAddress((void**)&ge2x, g_e2x);
    float* gx1;  cudaGetSymbolAddress((void**)&gx1,  g_x1);
    float* ge1x; cudaGetSymbolAddress((void**)&ge1x, g_e1x);
    float* gp0;  cudaGetSymbolAddress((void**)&gp0,  g_p0);
    float* gemb2;cudaGetSymbolAddress((void**)&gemb2,g_emb2);
    float* gw3;  cudaGetSymbolAddress((void**)&gw3,  g_wtT3);
    float* gw2;  cudaGetSymbolAddress((void**)&gw2,  g_wtT2);
    float* gw1;  cudaGetSymbolAddress((void**)&gw1,  g_wtT1);
    void *pAh, *pAl, *pWh, *pWl;
    cudaGetSymbolAddress(&pAh, g_Ah);
    cudaGetSymbolAddress(&pAl, g_Al);
    cudaGetSymbolAddress(&pWh, g_Wh);
    cudaGetSymbolAddress(&pWl, g_Wl);

    cudaFuncSetAttribute(k_gru, cudaFuncAttributeMaxDynamicSharedMemorySize, GRU_SMEM);

    static cudaStream_t s2 = nullptr;
    static cudaEvent_t evF = nullptr, evJ = nullptr;
    if (s2 == nullptr) {
        cudaStreamCreateWithFlags(&s2, cudaStreamNonBlocking);
        cudaEventCreateWithFlags(&evF, cudaEventDisableTiming);
        cudaEventCreateWithFlags(&evJ, cudaEventDisableTiming);
    }

    // fork side stream: weight transposes + skip-free pconv GEMMs (independent
    // of GRU; run on FMA pipe while GRU occupies mma pipe + barriers)
    cudaEventRecord(evF, 0);
    cudaStreamWaitEvent(s2, evF, 0);
    k_wtT<<<192, 256, 0, s2>>>(wt3, gw3);
    k_wtT<<<192, 256, 0, s2>>>(wt2, gw2);
    k_wtT<<<192, 256, 0, s2>>>(wt1, gw1);
    k_pconvP<<<dim3(64, 8),  256, 0, s2>>>(gx3, e3, w3p, b3p, TT * 8);
    k_pconvP<<<dim3(128, 8), 256, 0, s2>>>(gx2, e2, w2p, b2p, TT * 16);
    k_pconvP<<<dim3(256, 8), 256, 0, s2>>>(gx1, e1, w1p, b1p, TT * 32);
    k_pconvP<<<dim3(512, 8), 256, 0, s2>>>(gp0, e0, w0p, b0p, TT * 64);
    cudaEventRecord(evJ, s2);

    // main stream: GRU pipeline
    k_split<<<4096, 256>>>((const float4*)emb,
                           (ushort4*)pAh, (ushort4*)pAl, 1048576);
    k_split<<<3072, 256>>>((const float4*)Wih,
                           (ushort4*)pWh, (ushort4*)pWl, 786432);
    k_xg_mma<<<dim3(48, 32), 256>>>(bih);
    k_reset<<<1, 32>>>();
    k_gru<<<GBLK, 256, GRU_SMEM>>>(h_erb, Whh, bhh, out + BB * TT * 64);

    // join, then the sequential convt chain with fused skip-adds
    cudaStreamWaitEvent(0, evJ, 0);
    k_convt<<<dim3(128, 8), 128>>>(ge3x, gx3, gemb2, gw3, bt3, 8, TT * 8);
    k_convt<<<dim3(256, 8), 128>>>(ge2x, gx2, ge3x, gw2, bt2, 16, TT * 16);
    k_convt<<<dim3(512, 8), 128>>>(ge1x, gx1, ge2x, gw1, bt1, 32, TT * 32);
    k_final_lite<<<dim3(512, 8), 256>>>(gp0, w0o, b0o, out);
}

// round 13
// speedup vs baseline: 1.2564x; 1.0677x over previous
#include <cuda_runtime.h>
#include <cuda_bf16.h>

#define BB 8
#define TT 512
#define CC 128
#define HH 1024
#define GBLK 148
#define GW 7

typedef unsigned long long ull;
typedef unsigned short ushort_t;

// ---------------- f32x2 helpers (decoder kernels) ----------------
__device__ __forceinline__ ull dup2(float x)
{
    ull r;
    asm("mov.b64 %0, {%1, %1};" : "=l"(r) : "f"(x));
    return r;
}
__device__ __forceinline__ ull ffma2(ull a, ull b, ull c)
{
    ull d;
    asm("fma.rn.f32x2 %0, %1, %2, %3;" : "=l"(d) : "l"(a), "l"(b), "l"(c));
    return d;
}
__device__ __forceinline__ float2 unpk2(ull v)
{
    float2 f;
    asm("mov.b64 {%0, %1}, %2;" : "=f"(f.x), "=f"(f.y) : "l"(v));
    return f;
}

// ---------------- static scratch ----------------
__device__ float g_xg[BB * TT * 3 * HH];
__device__ ushort_t g_hhi[2][BB * HH];
__device__ ushort_t g_hlo[2][BB * HH];
__device__ float g_emb2[BB * CC * TT * 8];
__device__ float g_x3[BB * CC * TT * 8];
__device__ float g_e3x[BB * CC * TT * 16];
__device__ float g_x2[BB * CC * TT * 16];
__device__ float g_e2x[BB * CC * TT * 32];
__device__ float g_x1[BB * CC * TT * 32];
__device__ float g_e1x[BB * CC * TT * 64];
__device__ float g_p0[BB * CC * TT * 64];
__device__ float g_wtT3[3 * CC * CC];
__device__ float g_wtT2[3 * CC * CC];
__device__ float g_wtT1[3 * CC * CC];
__device__ unsigned short g_Ah[BB * TT * HH];
__device__ unsigned short g_Al[BB * TT * HH];
__device__ unsigned short g_Wh[3 * HH * HH];
__device__ unsigned short g_Wl[3 * HH * HH];
__device__ unsigned g_bar_count;
__device__ unsigned g_bar_gen;

// ---------------- barrier state reset (per launch) ----------------
__global__ void k_reset()
{
    if (threadIdx.x == 0) { g_bar_count = 0; g_bar_gen = 0; }
}

// ---------------- acquire/release grid barrier ----------------
__device__ __forceinline__ void grid_barrier(unsigned my_gen)
{
    __syncthreads();
    if (threadIdx.x == 0) {
        unsigned arr;
        asm volatile("atom.add.release.gpu.u32 %0, [%1], 1;"
                     : "=r"(arr) : "l"(&g_bar_count) : "memory");
        if (arr == GBLK - 1) {
            g_bar_count = 0;
            asm volatile("st.release.gpu.u32 [%0], %1;"
                         :: "l"(&g_bar_gen), "r"(my_gen) : "memory");
        } else {
            unsigned cur;
            do {
                asm volatile("ld.acquire.gpu.u32 %0, [%1];"
                             : "=r"(cur) : "l"(&g_bar_gen) : "memory");
            } while ((int)(cur - my_gen) < 0);
        }
    }
    __syncthreads();
}

// ---------------- splitting helper ----------------
__device__ __forceinline__ void split1(float v, unsigned short& h, unsigned short& l)
{
    __nv_bfloat16 bh = __float2bfloat16(v);
    float r = v - __bfloat162float(bh);
    __nv_bfloat16 bl = __float2bfloat16(r);
    h = *(unsigned short*)&bh;
    l = *(unsigned short*)&bl;
}

// ---------------- bf16 hi/lo split: fp32 tensor -> (hi, lo) ----------------
__global__ __launch_bounds__(256) void k_split(const float4* __restrict__ src,
                                               ushort4* __restrict__ hi,
                                               ushort4* __restrict__ lo,
                                               int n4)
{
    int i = blockIdx.x * 256 + threadIdx.x;
    if (i >= n4) return;
    float4 v = src[i];
    float f[4] = { v.x, v.y, v.z, v.w };
    unsigned short h[4], l[4];
#pragma unroll
    for (int q = 0; q < 4; ++q) split1(f[q], h[q], l[q]);
    hi[i] = make_ushort4(h[0], h[1], h[2], h[3]);
    lo[i] = make_ushort4(l[0], l[1], l[2], l[3]);
}

// ---------------- mma helpers (sm_80-baseline PTX) ----------------
__device__ __forceinline__ unsigned smem_u32(const void* p)
{
    unsigned a;
    asm("{ .reg .u64 t; cvta.to.shared.u64 t, %1; cvt.u32.u64 %0, t; }"
        : "=r"(a) : "l"(p));
    return a;
}
__device__ __forceinline__ void ldsm4(unsigned* r, unsigned addr)
{
    asm volatile("ldmatrix.sync.aligned.m8n8.x4.shared.b16 {%0,%1,%2,%3}, [%4];"
        : "=r"(r[0]), "=r"(r[1]), "=r"(r[2]), "=r"(r[3]) : "r"(addr));
}
__device__ __forceinline__ void ldsm2(unsigned* r, unsigned addr)
{
    asm volatile("ldmatrix.sync.aligned.m8n8.x2.shared.b16 {%0,%1}, [%2];"
        : "=r"(r[0]), "=r"(r[1]) : "r"(addr));
}
__device__ __forceinline__ void mma16816(float* d, const unsigned* a, const unsigned* b)
{
    asm volatile("mma.sync.aligned.m16n8k16.row.col.f32.bf16.bf16.f32 "
        "{%0,%1,%2,%3}, {%4,%5,%6,%7}, {%8,%9}, {%0,%1,%2,%3};"
        : "+f"(d[0]), "+f"(d[1]), "+f"(d[2]), "+f"(d[3])
        : "r"(a[0]), "r"(a[1]), "r"(a[2]), "r"(a[3]), "r"(b[0]), "r"(b[1]));
}

// ---------------- xg = emb @ Wih^T + bih : mma.sync split-bf16 ----------------
__global__ __launch_bounds__(256) void k_xg_mma(const float* __restrict__ bias)
{
    __shared__ __align__(16) unsigned short sAh[128][40];
    __shared__ __align__(16) unsigned short sAl[128][40];
    __shared__ __align__(16) unsigned short sWh[64][40];
    __shared__ __align__(16) unsigned short sWl[64][40];
    int tid = threadIdx.x, lane = tid & 31, wid = tid >> 5;
    int wm = wid >> 1, wn = wid & 1;
    int m0 = blockIdx.y * 128, n0 = blockIdx.x * 64;

    float acc[2][4][4];
#pragma unroll
    for (int mi = 0; mi < 2; ++mi)
#pragma unroll
        for (int ni = 0; ni < 4; ++ni)
#pragma unroll
            for (int q = 0; q < 4; ++q) acc[mi][ni][q] = 0.f;

    for (int kc = 0; kc < HH; kc += 32) {
        __syncthreads();
#pragma unroll
        for (int i = 0; i < 6; ++i) {
            int idx = tid + i * 256;
            const uint4* src;
            unsigned short* dst;
            if (idx < 512) {
                int row = idx >> 2, c8 = (idx & 3) * 8;
                src = (const uint4*)&g_Ah[(size_t)(m0 + row) * HH + kc + c8];
                dst = &sAh[row][c8];
            } else if (idx < 1024) {
                int e = idx - 512;
                int row = e >> 2, c8 = (e & 3) * 8;
                src = (const uint4*)&g_Al[(size_t)(m0 + row) * HH + kc + c8];
                dst = &sAl[row][c8];
            } else if (idx < 1280) {
                int e = idx - 1024;
                int row = e >> 2, c8 = (e & 3) * 8;
                src = (const uint4*)&g_Wh[(size_t)(n0 + row) * HH + kc + c8];
                dst = &sWh[row][c8];
            } else {
                int e = idx - 1280;
                int row = e >> 2, c8 = (e & 3) * 8;
                src = (const uint4*)&g_Wl[(size_t)(n0 + row) * HH + kc + c8];
                dst = &sWl[row][c8];
            }
            *(uint4*)dst = *src;
        }
        __syncthreads();

#pragma unroll
        for (int ks = 0; ks < 2; ++ks) {
            int k0 = ks * 16;
            unsigned ah[2][4], al[2][4];
#pragma unroll
            for (int mi = 0; mi < 2; ++mi) {
                int m = wm * 32 + mi * 16 + (lane & 15);
                int kk = k0 + (lane >> 4) * 8;
                ldsm4(ah[mi], smem_u32(&sAh[m][kk]));
                ldsm4(al[mi], smem_u32(&sAl[m][kk]));
            }
            unsigned bh[4][2], bl[4][2];
#pragma unroll
            for (int ni = 0; ni < 4; ++ni) {
                int r = lane & 15;
                int n = wn * 32 + ni * 8 + (r & 7);
                int kk = k0 + (r >> 3) * 8;
                ldsm2(bh[ni], smem_u32(&sWh[n][kk]));
                ldsm2(bl[ni], smem_u32(&sWl[n][kk]));
            }
#pragma unroll
            for (int mi = 0; mi < 2; ++mi)
#pragma unroll
                for (int ni = 0; ni < 4; ++ni) {
                    mma16816(acc[mi][ni], ah[mi], bh[ni]);
                    mma16816(acc[mi][ni], ah[mi], bl[ni]);
                    mma16816(acc[mi][ni], al[mi], bh[ni]);
                }
        }
    }
    int gr = lane >> 2, gc = (lane & 3) * 2;
#pragma unroll
    for (int mi = 0; mi < 2; ++mi)
#pragma unroll
        for (int ni = 0; ni < 4; ++ni) {
            int m = m0 + wm * 32 + mi * 16 + gr;
            int n = n0 + wn * 32 + ni * 8 + gc;
            float b0 = bias[n], b1 = bias[n + 1];
            float2 v0 = { acc[mi][ni][0] + b0, acc[mi][ni][1] + b1 };
            float2 v1 = { acc[mi][ni][2] + b0, acc[mi][ni][3] + b1 };
            *(float2*)&g_xg[(size_t)m * (3 * HH) + n] = v0;
            *(float2*)&g_xg[(size_t)(m + 8) * (3 * HH) + n] = v1;
        }
}

// ---------------- persistent GRU: reg-resident weight fragments ----------------
// Block owns 7 units -> 21 weight rows padded to 32. Per-warp K-window = 128.
// Weight fragments hoisted to registers (loaded once via smem staging).
// h stored pre-split (bf16 hi/lo) in global; epilogue keeps exact fp32 hprev in reg.
#define GRU_STRIDE 1032
#define OFF_HH 0
#define OFF_HL 16512
#define OFF_RED 33024
#define OFF_G 41216
#define GRU_SMEM 42240
#define ST_STRIDE 136

__global__ __launch_bounds__(256) void k_gru(const float* __restrict__ h0,
                                             const float* __restrict__ Whh,
                                             const float* __restrict__ bhh,
                                             float* __restrict__ outHT)
{
    extern __shared__ char gsm[];
    ushort_t (*sHh)[GRU_STRIDE] = (ushort_t(*)[GRU_STRIDE])(gsm + OFF_HH);
    ushort_t (*sHl)[GRU_STRIDE] = (ushort_t(*)[GRU_STRIDE])(gsm + OFF_HL);
    float (*sRed)[32][8] = (float(*)[32][8])(gsm + OFF_RED);
    float (*sG)[8] = (float(*)[8])(gsm + OFF_G);
    // prologue-only staging buffers alias the sH region (used before any h write)
    ushort_t (*stH)[ST_STRIDE] = (ushort_t(*)[ST_STRIDE])(gsm + 0);
    ushort_t (*stL)[ST_STRIDE] = (ushort_t(*)[ST_STRIDE])(gsm + 32 * ST_STRIDE * 2);

    int tid = threadIdx.x, lane = tid & 31, wid = tid >> 5;

    int eu = tid >> 3, eb = tid & 7;
    int ej = blockIdx.x * GW + eu;
    bool epv = (tid < 56) && (ej < HH);
    float br_ = 0.f, bz_ = 0.f, bn_ = 0.f, hprev = 0.f;
    int ec = ej & 127, ef = ej >> 7;
    if (epv) {
        br_ = bhh[ej]; bz_ = bhh[ej + HH]; bn_ = bhh[ej + 2 * HH];
        hprev = h0[eb * HH + ej];
    }

    // ---- prologue: load weight fragments into registers via staged chunks ----
    unsigned ah[8][2][4], al[8][2][4];
    for (int c = 0; c < 8; ++c) {
        __syncthreads();
        for (int idx = tid; idx < 4096; idx += 256) {
            int row = idx >> 7, x = idx & 127;
            float v = 0.f;
            if (row < 21) {
                int unit = row / 3, gate = row - unit * 3;
                int j = blockIdx.x * GW + unit;
                if (j < HH) v = Whh[(size_t)(j + gate * HH) * HH + c * 128 + x];
            }
            unsigned short h, l;
            split1(v, h, l);
            stH[row][x] = h;
            stL[row][x] = l;
        }
        __syncthreads();
        if (wid == c) {
#pragma unroll
            for (int ks = 0; ks < 8; ++ks)
#pragma unroll
                for (int mi = 0; mi < 2; ++mi) {
                    int m = mi * 16 + (lane & 15);
                    int col = ks * 16 + (lane >> 4) * 8;
                    ldsm4(ah[ks][mi], smem_u32(&stH[m][col]));
                    ldsm4(al[ks][mi], smem_u32(&stL[m][col]));
                }
        }
    }
    __syncthreads();

    // ---- init split h0 into global double buffer ----
    unsigned my_gen = 0;
    {
        int i = blockIdx.x * 256 + tid;
        if (i < BB * HH) {
            unsigned short h, l;
            split1(h0[i], h, l);
            g_hhi[0][i] = h;
            g_hlo[0][i] = l;
        }
    }
    ++my_gen;
    grid_barrier(my_gen);

    int kbase = wid * 128;

    for (int t = 0; t < TT; ++t) {
        float xr = 0.f, xz = 0.f, xn = 0.f;
        if (epv) {
            const float* xgp = g_xg + ((size_t)eb * TT + t) * (3 * HH);
            xr = xgp[ej]; xz = xgp[ej + HH]; xn = xgp[ej + 2 * HH];
        }
        // copy pre-split h into smem (no conversion)
        {
            const uint4* hi = (const uint4*)&g_hhi[t & 1][0];
            const uint4* lo = (const uint4*)&g_hlo[t & 1][0];
#pragma unroll
            for (int i = 0; i < 4; ++i) {
                int idx = tid + i * 256;             // < 1024
                int b = idx >> 7, k8 = (idx & 127) * 8;
                *(uint4*)&sHh[b][k8] = hi[idx];
                *(uint4*)&sHl[b][k8] = lo[idx];
            }
        }
        __syncthreads();

        float a0[2][4], a1[2][4], a2[2][4];
#pragma unroll
        for (int mi = 0; mi < 2; ++mi)
#pragma unroll
            for (int q = 0; q < 4; ++q) { a0[mi][q] = 0.f; a1[mi][q] = 0.f; a2[mi][q] = 0.f; }

#pragma unroll
        for (int ks = 0; ks < 8; ++ks) {
            int kk = kbase + ks * 16;
            unsigned bh[2], bl[2];
            int r = lane & 15;
            ldsm2(bh, smem_u32(&sHh[r & 7][kk + (r >> 3) * 8]));
            ldsm2(bl, smem_u32(&sHl[r & 7][kk + (r >> 3) * 8]));
#pragma unroll
            for (int mi = 0; mi < 2; ++mi) {
                mma16816(a0[mi], ah[ks][mi], bh);
                mma16816(a1[mi], ah[ks][mi], bl);
                mma16816(a2[mi], al[ks][mi], bh);
            }
        }
        int gr = lane >> 2, gc = (lane & 3) * 2;
#pragma unroll
        for (int mi = 0; mi < 2; ++mi) {
            sRed[wid][mi * 16 + gr][gc]         = a0[mi][0] + a1[mi][0] + a2[mi][0];
            sRed[wid][mi * 16 + gr][gc + 1]     = a0[mi][1] + a1[mi][1] + a2[mi][1];
            sRed[wid][mi * 16 + gr + 8][gc]     = a0[mi][2] + a1[mi][2] + a2[mi][2];
            sRed[wid][mi * 16 + gr + 8][gc + 1] = a0[mi][3] + a1[mi][3] + a2[mi][3];
        }
        __syncthreads();
        {
            int row = tid >> 3, col = tid & 7;
            float s = 0.f;
#pragma unroll
            for (int w = 0; w < 8; ++w) s += sRed[w][row][col];
            sG[row][col] = s;
        }
        __syncthreads();
        if (epv) {
            float sr = sG[eu * 3 + 0][eb];
            float sz = sG[eu * 3 + 1][eb];
            float sn = sG[eu * 3 + 2][eb];
            float r = 1.f / (1.f + __expf(-(xr + sr + br_)));
            float z = 1.f / (1.f + __expf(-(xz + sz + bz_)));
            float n = tanhf(xn + r * (sn + bn_));
            float hnew = (1.f - z) * n + z * hprev;
            hprev = hnew;
            unsigned short hh_, hl_;
            split1(hnew, hh_, hl_);
            g_hhi[(t + 1) & 1][eb * HH + ej] = hh_;
            g_hlo[(t + 1) & 1][eb * HH + ej] = hl_;
            g_emb2[((size_t)(eb * CC + ec) * TT + t) * 8 + ef] = hnew;
            if (t == TT - 1) outHT[eb * HH + ej] = hnew;
        }
        ++my_gen;
        grid_barrier(my_gen);
    }
}

// ---------------- pconvP: P = W @ x + bias (no skip), f32x2 ----------------
__global__ __launch_bounds__(256) void k_pconvP(float* __restrict__ out,
                                                const float* __restrict__ in,
                                                const float* __restrict__ W,
                                                const float* __restrict__ bias,
                                                int TF)
{
    __shared__ __align__(16) float Xs[128][64];
    __shared__ __align__(16) float Ws[16][128];
    int tid = threadIdx.x;
    int tx = tid & 15, ty = tid >> 4;
    int b = blockIdx.y;
    int p0 = blockIdx.x * 64;

#pragma unroll
    for (int i = 0; i < 8; ++i) {
        int e4 = tid + i * 256;
        int ch = e4 >> 4, pq = (e4 & 15) << 2;
        *(float4*)&Xs[ch][pq] = *(const float4*)&in[(size_t)(b * CC + ch) * TF + p0 + pq];
    }
    ull acc2[4][4];
#pragma unroll
    for (int p = 0; p < 4; ++p)
#pragma unroll
        for (int q = 0; q < 4; ++q) acc2[p][q] = 0ull;

    for (int kb = 0; kb < CC; kb += 16) {
#pragma unroll
        for (int i = 0; i < 2; ++i) {
            int e4 = tid * 2 + i;
            int oc = e4 >> 2, k4 = (e4 & 3) << 2;
            float4 v = *(const float4*)&W[oc * CC + kb + k4];
            Ws[k4 + 0][oc] = v.x; Ws[k4 + 1][oc] = v.y;
            Ws[k4 + 2][oc] = v.z; Ws[k4 + 3][oc] = v.w;
        }
        __syncthreads();
#pragma unroll
        for (int kk = 0; kk < 16; ++kk) {
            float4 xv = *(const float4*)&Xs[kb + kk][tx * 4];
            ull dx[4];
            dx[0] = dup2(xv.x); dx[1] = dup2(xv.y);
            dx[2] = dup2(xv.z); dx[3] = dup2(xv.w);
            ull wp[4];
#pragma unroll
            for (int p = 0; p < 4; ++p)
                wp[p] = *(const ull*)&Ws[kk][ty * 8 + 2 * p];
#pragma unroll
            for (int p = 0; p < 4; ++p)
#pragma unroll
                for (int q = 0; q < 4; ++q)
                    acc2[p][q] = ffma2(wp[p], dx[q], acc2[p][q]);
        }
        __syncthreads();
    }
#pragma unroll
    for (int p = 0; p < 4; ++p) {
        int oc0 = ty * 8 + 2 * p, oc1 = oc0 + 1;
        float2 u0 = unpk2(acc2[p][0]), u1 = unpk2(acc2[p][1]);
        float2 u2 = unpk2(acc2[p][2]), u3 = unpk2(acc2[p][3]);
        size_t i0 = (size_t)(b * CC + oc0) * TF + p0 + tx * 4;
        size_t i1 = (size_t)(b * CC + oc1) * TF + p0 + tx * 4;
        float bv0 = bias[oc0], bv1 = bias[oc1];
        float4 o0, o1;
        o0.x = u0.x + bv0; o0.y = u1.x + bv0;
        o0.z = u2.x + bv0; o0.w = u3.x + bv0;
        o1.x = u0.y + bv1; o1.y = u1.y + bv1;
        o1.z = u2.y + bv1; o1.w = u3.y + bv1;
        *(float4*)&out[i0] = o0;
        *(float4*)&out[i1] = o1;
    }
}

// ---------------- weight transpose for convt ----------------
__global__ __launch_bounds__(256) void k_wtT(const float* __restrict__ src,
                                             float* __restrict__ dst)
{
    int i = blockIdx.x * 256 + threadIdx.x;
    if (i < 3 * CC * CC) {
        int oc = i & 127, ic = (i >> 7) & 127, tap = i >> 14;
        dst[i] = src[(oc * CC + ic) * 3 + tap];
    }
}

// ---------------- convt (k=3,s=2) + ReLU, fused skip-add input, f32x2 ---------
__global__ __launch_bounds__(128) void k_convt(float* __restrict__ out,
                                               const float* __restrict__ in,
                                               const float* __restrict__ skip,
                                               const float* __restrict__ wT,
                                               const float* __restrict__ bias,
                                               int Fin, int TF)
{
    __shared__ __align__(16) float Xs[128][36];
    __shared__ __align__(16) float Ws[3][16][128];
    int tid = threadIdx.x;
    int tx = tid & 7, ty = tid >> 3;
    int b = blockIdx.y;
    int p0 = blockIdx.x * 32;

#pragma unroll
    for (int i = 0; i < 8; ++i) {
        int e4 = tid + i * 128;
        int ch = e4 >> 3, pq = (e4 & 7) << 2;
        size_t gi = (size_t)(b * CC + ch) * TF + p0 + pq;
        float4 a = *(const float4*)&in[gi];
        float4 s = *(const float4*)&skip[gi];
        a.x += s.x; a.y += s.y; a.z += s.z; a.w += s.w;
        *(float4*)&Xs[ch][pq] = a;
    }
    int p_ = tx * 4;
    bool sh[4];
#pragma unroll
    for (int jj = 0; jj < 4; ++jj) sh[jj] = (((p_ + jj) & (Fin - 1)) != Fin - 1);

    ull ae2[4][4], ao2[4][4];
#pragma unroll
    for (int p = 0; p < 4; ++p)
#pragma unroll
        for (int q = 0; q < 4; ++q) { ae2[p][q] = 0ull; ao2[p][q] = 0ull; }

    for (int kb = 0; kb < CC; kb += 16) {
        __syncthreads();
#pragma unroll
        for (int i = 0; i < 12; ++i) {
            int idx = tid + i * 128;
            int tap = idx / 512, rem = idx & 511;
            int kkk = rem >> 5, oc4 = (rem & 31) << 2;
            *(float4*)&Ws[tap][kkk][oc4] =
                *(const float4*)&wT[(tap * CC + kb + kkk) * CC + oc4];
        }
        __syncthreads();
#pragma unroll
        for (int kk = 0; kk < 16; ++kk) {
            const float* xrow = &Xs[kb + kk][0];
            float4 xv = *(const float4*)&xrow[p_];
            float xnext = xrow[p_ + 4];
            ull dx[4], dxs[4];
            dx[0] = dup2(xv.x); dx[1] = dup2(xv.y);
            dx[2] = dup2(xv.z); dx[3] = dup2(xv.w);
            dxs[0] = dup2(sh[0] ? xv.y : 0.f);
            dxs[1] = dup2(sh[1] ? xv.z : 0.f);
            dxs[2] = dup2(sh[2] ? xv.w : 0.f);
            dxs[3] = dup2(sh[3] ? xnext : 0.f);
            ull w0p[4], w1p[4], w2p[4];
#pragma unroll
            for (int p = 0; p < 4; ++p) {
                w0p[p] = *(const ull*)&Ws[0][kk][ty * 8 + 2 * p];
                w1p[p] = *(const ull*)&Ws[1][kk][ty * 8 + 2 * p];
                w2p[p] = *(const ull*)&Ws[2][kk][ty * 8 + 2 * p];
            }
#pragma unroll
            for (int p = 0; p < 4; ++p)
#pragma unroll
                for (int q = 0; q < 4; ++q) {
                    ae2[p][q] = ffma2(w1p[p], dx[q], ae2[p][q]);
                    ao2[p][q] = ffma2(w0p[p], dx[q], ao2[p][q]);
                    ao2[p][q] = ffma2(w2p[p], dxs[q], ao2[p][q]);
                }
        }
    }
    int TF2 = TF * 2;
#pragma unroll
    for (int p = 0; p < 4; ++p) {
        int oc0 = ty * 8 + 2 * p, oc1 = oc0 + 1;
        float bv0 = bias[oc0], bv1 = bias[oc1];
#pragma unroll
        for (int q = 0; q < 4; ++q) {
            int pp = p0 + p_ + q;
            float2 e = unpk2(ae2[p][q]);
            float2 o = unpk2(ao2[p][q]);
            float2 r0, r1;
            r0.x = fmaxf(e.x + bv0, 0.f); r0.y = fmaxf(o.x + bv0, 0.f);
            r1.x = fmaxf(e.y + bv1, 0.f); r1.y = fmaxf(o.y + bv1, 0.f);
            *(float2*)&out[(size_t)(b * CC + oc0) * TF2 + 2 * pp] = r0;
            *(float2*)&out[(size_t)(b * CC + oc1) * TF2 + 2 * pp] = r1;
        }
    }
}

// ---------------- final lite: pre = P0 + e1x ; m = sigmoid(conv3(pre)) -------
__global__ __launch_bounds__(256) void k_final_lite(const float* __restrict__ P0,
                                                    const float* __restrict__ w0o,
                                                    const float* __restrict__ b0o,
                                                    float* __restrict__ outm)
{
    __shared__ __align__(16) float pre[128][68];
    __shared__ float wo[128][3];
    const int TF = TT * 64;
    int tid = threadIdx.x;
    int b = blockIdx.y, t = blockIdx.x;
    int p0 = t * 64;

    for (int i = tid; i < 384; i += 256) wo[i / 3][i % 3] = w0o[i];
#pragma unroll
    for (int i = 0; i < 8; ++i) {
        int e4 = tid + i * 256;
        int ch = e4 >> 4, pq = (e4 & 15) << 2;
        size_t gi = (size_t)(b * CC + ch) * TF + p0 + pq;
        float4 a = *(const float4*)&P0[gi];
        float4 s = *(const float4*)&g_e1x[gi];
        a.x += s.x; a.y += s.y; a.z += s.z; a.w += s.w;
        *(float4*)&pre[ch][pq] = a;
    }
    __syncthreads();
    int f = tid >> 2, q = tid & 3;
    float s = 0.f;
#pragma unroll 4
    for (int i = 0; i < 32; ++i) {
        int ch = q * 32 + i;
        float x0 = pre[ch][f];
        float xm = (f > 0) ? pre[ch][f - 1] : 0.f;
        float xp = (f < 63) ? pre[ch][f + 1] : 0.f;
        s = fmaf(wo[ch][0], xm, s);
        s = fmaf(wo[ch][1], x0, s);
        s = fmaf(wo[ch][2], xp, s);
    }
    s += __shfl_down_sync(0xffffffffu, s, 1);
    s += __shfl_down_sync(0xffffffffu, s, 2);
    if (q == 0) outm[((size_t)b * TT + t) * 64 + f] = 1.f / (1.f + __expf(-(s + b0o[0])));
}

// ---------------------------------- launch ----------------------------------
extern "C" void kernel_launch(void* const* d_in, const int* in_sizes, int n_in,
                              void* d_out, int out_size)
{
    const float* emb   = (const float*)d_in[0];
    const float* e3    = (const float*)d_in[1];
    const float* e2    = (const float*)d_in[2];
    const float* e1    = (const float*)d_in[3];
    const float* e0    = (const float*)d_in[4];
    const float* h_erb = (const float*)d_in[5];
    const float* Wih   = (const float*)d_in[6];
    const float* Whh   = (const float*)d_in[7];
    const float* bih   = (const float*)d_in[8];
    const float* bhh   = (const float*)d_in[9];
    const float* w3p   = (const float*)d_in[10];
    const float* b3p   = (const float*)d_in[11];
    const float* w2p   = (const float*)d_in[12];
    const float* b2p   = (const float*)d_in[13];
    const float* w1p   = (const float*)d_in[14];
    const float* b1p   = (const float*)d_in[15];
    const float* w0p   = (const float*)d_in[16];
    const float* b0p   = (const float*)d_in[17];
    const float* wt3   = (const float*)d_in[18];
    const float* bt3   = (const float*)d_in[19];
    const float* wt2   = (const float*)d_in[20];
    const float* bt2   = (const float*)d_in[21];
    const float* wt1   = (const float*)d_in[22];
    const float* bt1   = (const float*)d_in[23];
    const float* w0o   = (const float*)d_in[24];
    const float* b0o   = (const float*)d_in[25];
    float* out = (float*)d_out;

    float* gx3;  cudaGetSymbolAddress((void**)&gx3,  g_x3);
    float* ge3x; cudaGetSymbolAddress((void**)&ge3x, g_e3x);
    float* gx2;  cudaGetSymbolAddress((void**)&gx2,  g_x2);
    float* ge2x; cudaGetSymbolAddress((void**)&ge2x, g_e2x);
    float* gx1;  cudaGetSymbolAddress((void**)&gx1,  g_x1);
    float* ge1x; cudaGetSymbolAddress((void**)&ge1x, g_e1x);
    float* gp0;  cudaGetSymbolAddress((void**)&gp0,  g_p0);
    float* gemb2;cudaGetSymbolAddress((void**)&gemb2,g_emb2);
    float* gw3;  cudaGetSymbolAddress((void**)&gw3,  g_wtT3);
    float* gw2;  cudaGetSymbolAddress((void**)&gw2,  g_wtT2);
    float* gw1;  cudaGetSymbolAddress((void**)&gw1,  g_wtT1);
    void *pAh, *pAl, *pWh, *pWl;
    cudaGetSymbolAddress(&pAh, g_Ah);
    cudaGetSymbolAddress(&pAl, g_Al);
    cudaGetSymbolAddress(&pWh, g_Wh);
    cudaGetSymbolAddress(&pWl, g_Wl);

    cudaFuncSetAttribute(k_gru, cudaFuncAttributeMaxDynamicSharedMemorySize, GRU_SMEM);

    static cudaStream_t s2 = nullptr;
    static cudaEvent_t evF = nullptr, evJ = nullptr;
    if (s2 == nullptr) {
        cudaStreamCreateWithFlags(&s2, cudaStreamNonBlocking);
        cudaEventCreateWithFlags(&evF, cudaEventDisableTiming);
        cudaEventCreateWithFlags(&evJ, cudaEventDisableTiming);
    }

    // side stream: weight transposes + skip-free pconv GEMMs
    cudaEventRecord(evF, 0);
    cudaStreamWaitEvent(s2, evF, 0);
    k_wtT<<<192, 256, 0, s2>>>(wt3, gw3);
    k_wtT<<<192, 256, 0, s2>>>(wt2, gw2);
    k_wtT<<<192, 256, 0, s2>>>(wt1, gw1);
    k_pconvP<<<dim3(64, 8),  256, 0, s2>>>(gx3, e3, w3p, b3p, TT * 8);
    k_pconvP<<<dim3(128, 8), 256, 0, s2>>>(gx2, e2, w2p, b2p, TT * 16);
    k_pconvP<<<dim3(256, 8), 256, 0, s2>>>(gx1, e1, w1p, b1p, TT * 32);
    k_pconvP<<<dim3(512, 8), 256, 0, s2>>>(gp0, e0, w0p, b0p, TT * 64);
    cudaEventRecord(evJ, s2);

    // main stream: GRU pipeline
    k_split<<<4096, 256>>>((const float4*)emb,
                           (ushort4*)pAh, (ushort4*)pAl, 1048576);
    k_split<<<3072, 256>>>((const float4*)Wih,
                           (ushort4*)pWh, (ushort4*)pWl, 786432);
    k_xg_mma<<<dim3(48, 32), 256>>>(bih);
    k_reset<<<1, 32>>>();
    k_gru<<<GBLK, 256, GRU_SMEM>>>(h_erb, Whh, bhh, out + BB * TT * 64);

    // join, then sequential convt chain with fused skip-adds
    cudaStreamWaitEvent(0, evJ, 0);
    k_convt<<<dim3(128, 8), 128>>>(ge3x, gx3, gemb2, gw3, bt3, 8, TT * 8);
    k_convt<<<dim3(256, 8), 128>>>(ge2x, gx2, ge3x, gw2, bt2, 16, TT * 16);
    k_convt<<<dim3(512, 8), 128>>>(ge1x, gx1, ge2x, gw1, bt1, 32, TT * 32);
    k_final_lite<<<dim3(512, 8), 256>>>(gp0, w0o, b0o, out);
}